// round 5
// baseline (speedup 1.0000x reference)
#include <cuda_runtime.h>
#include <cuda_bf16.h>
#include <cstdint>
#include <math.h>

#define BB 4
#define SS 2048
#define DD 1024

#define LDBY 80                    // smem row stride bytes (64B data + 16B pad)
#define TILE_A_B (256 * LDBY)      // 20480 B : 256x32 bf16 tile
#define TILE_B_B (128 * LDBY)      // 10240 B : 128x32 bf16 tile
#define STAGE_B (2 * TILE_A_B + 2 * TILE_B_B)   // Ah, Al, Bh, Bl = 61440
#define NSTAGE 3
#define SMEM_BYTES (NSTAGE * STAGE_B)           // 184320

// ---------------------------------------------------------------------------
// Scratch (__device__ globals; allocation-free rule)
// ---------------------------------------------------------------------------
__device__ __align__(16) __nv_bfloat16 g_x_hi[BB*SS*DD], g_x_lo[BB*SS*DD];
__device__ __align__(16) __nv_bfloat16 g_w_hi[3][DD*DD], g_w_lo[3][DD*DD];
__device__ __align__(16) __nv_bfloat16 g_q_hi[BB*SS*DD], g_q_lo[BB*SS*DD];
__device__ __align__(16) __nv_bfloat16 g_k_hi[BB*SS*DD], g_k_lo[BB*SS*DD];
__device__ __align__(16) __nv_bfloat16 g_vT_hi[BB*DD*SS], g_vT_lo[BB*DD*SS];  // [b][d][s]
__device__ __align__(16) float g_p[(size_t)BB*SS*SS];
__device__ __align__(16) __nv_bfloat16 g_p_hi[BB*SS*SS], g_p_lo[BB*SS*SS];

// ---------------------------------------------------------------------------
// PTX primitives
// ---------------------------------------------------------------------------
__device__ __forceinline__ void mma_bf16(float* d, const uint32_t* a, const uint32_t* b) {
    asm volatile(
        "mma.sync.aligned.m16n8k16.row.col.f32.bf16.bf16.f32 "
        "{%0,%1,%2,%3}, {%4,%5,%6,%7}, {%8,%9}, {%0,%1,%2,%3};"
        : "+f"(d[0]), "+f"(d[1]), "+f"(d[2]), "+f"(d[3])
        : "r"(a[0]), "r"(a[1]), "r"(a[2]), "r"(a[3]), "r"(b[0]), "r"(b[1]));
}
#define LDSM4(r0, r1, r2, r3, addr) \
    asm volatile("ldmatrix.sync.aligned.m8n8.x4.shared.b16 {%0,%1,%2,%3}, [%4];" \
                 : "=r"(r0), "=r"(r1), "=r"(r2), "=r"(r3) : "r"(addr))
#define CP_ASYNC16(dst, src) \
    asm volatile("cp.async.cg.shared.global [%0], [%1], 16;" :: "r"(dst), "l"(src))
#define CP_COMMIT() asm volatile("cp.async.commit_group;" ::: "memory")
#define CP_WAIT2()  asm volatile("cp.async.wait_group 2;" ::: "memory")

// ---------------------------------------------------------------------------
// cp.async tile loaders: rows x 32 bf16 (K-major, row stride ld elems)
// 256 threads
// ---------------------------------------------------------------------------
__device__ __forceinline__ void g2s_256(uint32_t dst, const __nv_bfloat16* __restrict__ g,
                                        size_t ld, int k0, int tid) {
#pragma unroll
    for (int i = 0; i < 4; i++) {
        int slot = tid + (i << 8);      // 0..1023
        int row = slot >> 2;            // 0..255
        int c = slot & 3;
        CP_ASYNC16(dst + row * LDBY + c * 16, g + (size_t)row * ld + k0 + c * 8);
    }
}
__device__ __forceinline__ void g2s_128(uint32_t dst, const __nv_bfloat16* __restrict__ g,
                                        size_t ld, int k0, int tid) {
#pragma unroll
    for (int i = 0; i < 2; i++) {
        int slot = tid + (i << 8);      // 0..511
        int row = slot >> 2;            // 0..127
        int c = slot & 3;
        CP_ASYNC16(dst + row * LDBY + c * 16, g + (size_t)row * ld + k0 + c * 8);
    }
}

__device__ __forceinline__ void load_stage(uint32_t st,
    const __nv_bfloat16* Ah, const __nv_bfloat16* Al,
    const __nv_bfloat16* Bh, const __nv_bfloat16* Bl,
    size_t lda, size_t ldb, int k0, int tid) {
    g2s_256(st,                Ah, lda, k0, tid);
    g2s_256(st + TILE_A_B,     Al, lda, k0, tid);
    g2s_128(st + 2*TILE_A_B,   Bh, ldb, k0, tid);
    g2s_128(st + 2*TILE_A_B + TILE_B_B, Bl, ldb, k0, tid);
}

// ---------------------------------------------------------------------------
// Mainloop: acc[4][8][4] += split3(A[256,K]) . split3(B[128,K])^T
// 256 threads, 8 warps in 4x2 grid, warp tile 64x64, 3-stage cp.async pipeline
// ---------------------------------------------------------------------------
__device__ __forceinline__ void mma_mainloop(
    const __nv_bfloat16* __restrict__ Ah, const __nv_bfloat16* __restrict__ Al,
    const __nv_bfloat16* __restrict__ Bh, const __nv_bfloat16* __restrict__ Bl,
    size_t lda, size_t ldb, int nch, uint32_t smem, float acc[4][8][4]) {

    const int tid = threadIdx.x;
    const int lane = tid & 31, wid = tid >> 5;
    const int wm = wid >> 1, wn = wid & 1;

    const uint32_t a_off = (uint32_t)(wm * 64 + (lane & 15)) * LDBY + ((lane & 16) ? 16u : 0u);
    const uint32_t b_off = (uint32_t)(wn * 64 + (lane & 7) + ((lane & 16) ? 8 : 0)) * LDBY
                         + ((lane & 8) ? 16u : 0u);

    // prologue: stages 0, 1
    load_stage(smem, Ah, Al, Bh, Bl, lda, ldb, 0, tid);
    CP_COMMIT();
    if (nch > 1) load_stage(smem + STAGE_B, Ah, Al, Bh, Bl, lda, ldb, 32, tid);
    CP_COMMIT();

    int sidx = 0;
    for (int c = 0; c < nch; c++) {
        if (c + 2 < nch) {
            int s2 = sidx + 2; if (s2 >= NSTAGE) s2 -= NSTAGE;
            load_stage(smem + s2 * STAGE_B, Ah, Al, Bh, Bl, lda, ldb, (c + 2) * 32, tid);
        }
        CP_COMMIT();
        CP_WAIT2();
        __syncthreads();

        const uint32_t st = smem + sidx * STAGE_B;
#pragma unroll
        for (int ks = 0; ks < 2; ks++) {
            const uint32_t ka = st + a_off + ks * 32;
            const uint32_t kb = st + 2 * TILE_A_B + b_off + ks * 32;
            uint32_t ah[4][4], bh[8][2], bl[8][2];
#pragma unroll
            for (int fm = 0; fm < 4; fm++)
                LDSM4(ah[fm][0], ah[fm][1], ah[fm][2], ah[fm][3], ka + fm * 16 * LDBY);
#pragma unroll
            for (int p = 0; p < 4; p++)
                LDSM4(bh[2*p][0], bh[2*p][1], bh[2*p+1][0], bh[2*p+1][1], kb + p * 16 * LDBY);
#pragma unroll
            for (int p = 0; p < 4; p++)
                LDSM4(bl[2*p][0], bl[2*p][1], bl[2*p+1][0], bl[2*p+1][1],
                      kb + TILE_B_B + p * 16 * LDBY);

            // term 1: Ah x Bh
#pragma unroll
            for (int fm = 0; fm < 4; fm++)
#pragma unroll
                for (int fn = 0; fn < 8; fn++) mma_bf16(acc[fm][fn], ah[fm], bh[fn]);
            // term 2: Ah x Bl
#pragma unroll
            for (int fm = 0; fm < 4; fm++)
#pragma unroll
                for (int fn = 0; fn < 8; fn++) mma_bf16(acc[fm][fn], ah[fm], bl[fn]);
            // term 3: Al x Bh (reload into ah regs)
#pragma unroll
            for (int fm = 0; fm < 4; fm++)
                LDSM4(ah[fm][0], ah[fm][1], ah[fm][2], ah[fm][3],
                      ka + TILE_A_B + fm * 16 * LDBY);
#pragma unroll
            for (int fm = 0; fm < 4; fm++)
#pragma unroll
                for (int fn = 0; fn < 8; fn++) mma_bf16(acc[fm][fn], ah[fm], bh[fn]);
        }
        __syncthreads();
        if (++sidx == NSTAGE) sidx = 0;
    }
}

#define ZERO_ACC(acc) \
    do { _Pragma("unroll") for (int i = 0; i < 4; i++) \
         _Pragma("unroll") for (int j = 0; j < 8; j++) \
         _Pragma("unroll") for (int r = 0; r < 4; r++) (acc)[i][j][r] = 0.0f; } while (0)

// ---------------------------------------------------------------------------
// Kernel 0: split fp32 -> (hi, lo) bf16 for x, Wq, Wk, Wv
// ---------------------------------------------------------------------------
__global__ __launch_bounds__(256) void split_all(
    const float* __restrict__ x, const float* __restrict__ wq,
    const float* __restrict__ wk, const float* __restrict__ wv) {
    const int which = blockIdx.y;
    const float* src = (which == 0) ? x : (which == 1) ? wq : (which == 2) ? wk : wv;
    __nv_bfloat16* hi = (which == 0) ? g_x_hi : g_w_hi[which - 1];
    __nv_bfloat16* lo = (which == 0) ? g_x_lo : g_w_lo[which - 1];
    const int n = (which == 0) ? BB * SS * DD : DD * DD;
    for (int i = blockIdx.x * 256 + threadIdx.x; i < n; i += gridDim.x * 256) {
        float f = src[i];
        __nv_bfloat16 h = __float2bfloat16(f);
        hi[i] = h;
        lo[i] = __float2bfloat16(f - __bfloat162float(h));
    }
}

// ---------------------------------------------------------------------------
// Kernel 1: QKV.  z=0 -> Q(split), z=1 -> K(split), z=2 -> V^T(split)
// M tile = 256 rows of x; N tile = 128 output dims
// ---------------------------------------------------------------------------
__global__ __launch_bounds__(256, 1) void qkv_mma() {
    extern __shared__ char smraw[];
    const uint32_t smem = (uint32_t)__cvta_generic_to_shared(smraw);
    const int z = blockIdx.z;
    const int m0 = blockIdx.y * 256;
    const int n0 = blockIdx.x * 128;

    float acc[4][8][4];
    ZERO_ACC(acc);

    mma_mainloop(g_x_hi + (size_t)m0 * DD, g_x_lo + (size_t)m0 * DD,
                 g_w_hi[z] + (size_t)n0 * DD, g_w_lo[z] + (size_t)n0 * DD,
                 DD, DD, DD / 32, smem, acc);

    const int lane = threadIdx.x & 31, wid = threadIdx.x >> 5;
    const int wm = wid >> 1, wn = wid & 1;
    const int g = lane >> 2, tg = lane & 3;

#pragma unroll
    for (int fm = 0; fm < 4; fm++)
#pragma unroll
        for (int fn = 0; fn < 8; fn++) {
            const int n = n0 + wn * 64 + fn * 8 + tg * 2;
#pragma unroll
            for (int half = 0; half < 2; half++) {
                const int m = m0 + wm * 64 + fm * 16 + g + half * 8;
                float f0 = acc[fm][fn][half * 2], f1 = acc[fm][fn][half * 2 + 1];
                if (z < 2) {
                    __nv_bfloat16* H = z ? g_k_hi : g_q_hi;
                    __nv_bfloat16* L = z ? g_k_lo : g_q_lo;
                    __nv_bfloat16 h0 = __float2bfloat16(f0), h1 = __float2bfloat16(f1);
                    __nv_bfloat162 h2; h2.x = h0; h2.y = h1;
                    __nv_bfloat162 l2;
                    l2.x = __float2bfloat16(f0 - __bfloat162float(h0));
                    l2.y = __float2bfloat16(f1 - __bfloat162float(h1));
                    *(__nv_bfloat162*)(H + (size_t)m * DD + n) = h2;
                    *(__nv_bfloat162*)(L + (size_t)m * DD + n) = l2;
                } else {
                    const int b = m >> 11, ml = m & (SS - 1);
                    const size_t vb = (size_t)b * DD * SS;
                    __nv_bfloat16 h0 = __float2bfloat16(f0), h1 = __float2bfloat16(f1);
                    g_vT_hi[vb + (size_t)n * SS + ml] = h0;
                    g_vT_lo[vb + (size_t)n * SS + ml] = __float2bfloat16(f0 - __bfloat162float(h0));
                    g_vT_hi[vb + (size_t)(n + 1) * SS + ml] = h1;
                    g_vT_lo[vb + (size_t)(n + 1) * SS + ml] = __float2bfloat16(f1 - __bfloat162float(h1));
                }
            }
        }
}

// ---------------------------------------------------------------------------
// Kernel 2: causal scores. 256x128 tiles, keep tiles with jt <= 2*it+1.
// per-batch count = sum_{it=0..7} (2it+2) = 72
// ---------------------------------------------------------------------------
__global__ __launch_bounds__(256, 1) void scores_mma() {
    extern __shared__ char smraw[];
    const uint32_t smem = (uint32_t)__cvta_generic_to_shared(smraw);
    const int t = blockIdx.x;
    // it(it+1) <= t < (it+1)(it+2)
    int it = (int)floorf((sqrtf(4.0f * (float)t + 1.0f) - 1.0f) * 0.5f);
    while ((it + 1) * (it + 2) <= t) ++it;
    while (it * (it + 1) > t) --it;
    const int jt = t - it * (it + 1);
    const int b = blockIdx.y;
    const int m0 = it * 256, n0 = jt * 128;

    float acc[4][8][4];
    ZERO_ACC(acc);

    const size_t ao = ((size_t)b * SS + m0) * DD;
    const size_t bo = ((size_t)b * SS + n0) * DD;
    mma_mainloop(g_q_hi + ao, g_q_lo + ao, g_k_hi + bo, g_k_lo + bo,
                 DD, DD, DD / 32, smem, acc);

    const int lane = threadIdx.x & 31, wid = threadIdx.x >> 5;
    const int wm = wid >> 1, wn = wid & 1;
    const int g = lane >> 2, tg = lane & 3;
    float* C = g_p + (size_t)b * SS * SS;
    const float alpha = 1.0f / 32.0f;

#pragma unroll
    for (int fm = 0; fm < 4; fm++)
#pragma unroll
        for (int fn = 0; fn < 8; fn++) {
            const int n = n0 + wn * 64 + fn * 8 + tg * 2;
#pragma unroll
            for (int half = 0; half < 2; half++) {
                const int m = m0 + wm * 64 + fm * 16 + g + half * 8;
                float2 v;
                v.x = acc[fm][fn][half * 2] * alpha;
                v.y = acc[fm][fn][half * 2 + 1] * alpha;
                *(float2*)(C + (size_t)m * SS + n) = v;
            }
        }
}

// ---------------------------------------------------------------------------
// Kernel 3: causal row softmax; emits split-bf16 P, zero-filled to 256 edge
// ---------------------------------------------------------------------------
__global__ __launch_bounds__(256) void softmax_rows() {
    const int i = blockIdx.x, b = blockIdx.y;
    const size_t rowoff = ((size_t)b * SS + i) * SS;
    float* row = g_p + rowoff;
    const int len = i + 1;
    const int tid = threadIdx.x, lane = tid & 31, wid = tid >> 5;

    __shared__ float red[8];
    __shared__ float s_max, s_sum;

    float m = -1e30f;
    for (int j = tid; j < len; j += 256) m = fmaxf(m, row[j]);
#pragma unroll
    for (int o = 16; o; o >>= 1) m = fmaxf(m, __shfl_xor_sync(0xffffffffu, m, o));
    if (lane == 0) red[wid] = m;
    __syncthreads();
    if (tid < 32) {
        float v = (tid < 8) ? red[tid] : -1e30f;
#pragma unroll
        for (int o = 4; o; o >>= 1) v = fmaxf(v, __shfl_xor_sync(0xffffffffu, v, o));
        if (tid == 0) s_max = v;
    }
    __syncthreads();
    m = s_max;

    float s = 0.0f;
    for (int j = tid; j < len; j += 256) {
        float e = __expf(row[j] - m);
        row[j] = e;
        s += e;
    }
#pragma unroll
    for (int o = 16; o; o >>= 1) s += __shfl_xor_sync(0xffffffffu, s, o);
    __syncthreads();
    if (lane == 0) red[wid] = s;
    __syncthreads();
    if (tid < 32) {
        float v = (tid < 8) ? red[tid] : 0.0f;
#pragma unroll
        for (int o = 4; o; o >>= 1) v += __shfl_xor_sync(0xffffffffu, v, o);
        if (tid == 0) s_sum = v;
    }
    __syncthreads();
    const float inv = 1.0f / s_sum;

    __nv_bfloat16* ph = g_p_hi + rowoff;
    __nv_bfloat16* pl = g_p_lo + rowoff;
    for (int j = tid; j < len; j += 256) {
        float p = row[j] * inv;
        __nv_bfloat16 h = __float2bfloat16(p);
        ph[j] = h;
        pl[j] = __float2bfloat16(p - __bfloat162float(h));
    }
    const int tend = ((i >> 8) + 1) << 8;   // ceil to 256 (pv M-tile)
    const __nv_bfloat16 z = __float2bfloat16(0.0f);
    for (int j = len + tid; j < tend; j += 256) { ph[j] = z; pl[j] = z; }
}

// ---------------------------------------------------------------------------
// Kernel 4: O = P @ V.  M tile 256 (it reversed: longest first), N tile 128.
// ---------------------------------------------------------------------------
__global__ __launch_bounds__(256, 1) void pv_mma(float* __restrict__ out) {
    extern __shared__ char smraw[];
    const uint32_t smem = (uint32_t)__cvta_generic_to_shared(smraw);
    const int b = blockIdx.z;
    const int it = (SS / 256 - 1) - blockIdx.y;   // 7..0, big tiles first
    const int m0 = it * 256;
    const int n0 = blockIdx.x * 128;
    const int nch = (it + 1) * 8;                 // kend = (it+1)*256

    float acc[4][8][4];
    ZERO_ACC(acc);

    const size_t ao = ((size_t)b * SS + m0) * SS;
    const size_t bo = (size_t)b * DD * SS + (size_t)n0 * SS;
    mma_mainloop(g_p_hi + ao, g_p_lo + ao, g_vT_hi + bo, g_vT_lo + bo,
                 SS, SS, nch, smem, acc);

    const int lane = threadIdx.x & 31, wid = threadIdx.x >> 5;
    const int wm = wid >> 1, wn = wid & 1;
    const int g = lane >> 2, tg = lane & 3;
    float* C = out + (size_t)b * SS * DD;

#pragma unroll
    for (int fm = 0; fm < 4; fm++)
#pragma unroll
        for (int fn = 0; fn < 8; fn++) {
            const int n = n0 + wn * 64 + fn * 8 + tg * 2;
#pragma unroll
            for (int half = 0; half < 2; half++) {
                const int m = m0 + wm * 64 + fm * 16 + g + half * 8;
                float2 v;
                v.x = acc[fm][fn][half * 2];
                v.y = acc[fm][fn][half * 2 + 1];
                *(float2*)(C + (size_t)m * DD + n) = v;
            }
        }
}

// ---------------------------------------------------------------------------
extern "C" void kernel_launch(void* const* d_in, const int* in_sizes, int n_in,
                              void* d_out, int out_size) {
    const float* x  = (const float*)d_in[0];
    const float* wq = (const float*)d_in[1];
    const float* wk = (const float*)d_in[2];
    const float* wv = (const float*)d_in[3];
    float* out = (float*)d_out;
    (void)in_sizes; (void)n_in; (void)out_size;

    static bool attr_done = false;
    if (!attr_done) {
        cudaFuncSetAttribute(qkv_mma,    cudaFuncAttributeMaxDynamicSharedMemorySize, SMEM_BYTES);
        cudaFuncSetAttribute(scores_mma, cudaFuncAttributeMaxDynamicSharedMemorySize, SMEM_BYTES);
        cudaFuncSetAttribute(pv_mma,     cudaFuncAttributeMaxDynamicSharedMemorySize, SMEM_BYTES);
        attr_done = true;
    }

    // 0) split inputs into bf16 hi/lo
    split_all<<<dim3(1024, 4), 256>>>(x, wq, wk, wv);

    // 1) Q, K, V^T projections
    qkv_mma<<<dim3(DD / 128, (BB * SS) / 256, 3), 256, SMEM_BYTES>>>();

    // 2) causal scores (trapezoid of 256x128 tiles: 72 per batch)
    scores_mma<<<dim3(72, BB), 256, SMEM_BYTES>>>();

    // 3) softmax -> split-bf16 P (zero-padded to 256)
    softmax_rows<<<dim3(SS, BB), 256>>>();

    // 4) O = P @ V
    pv_mma<<<dim3(DD / 128, SS / 256, BB), 256, SMEM_BYTES>>>(out);
}

// round 6
// speedup vs baseline: 1.5435x; 1.5435x over previous
#include <cuda_runtime.h>
#include <cuda_fp16.h>
#include <cstdint>
#include <math.h>

#define BB 4
#define SS 2048
#define DD 1024

#define LDBY 80                     // smem row stride bytes (64B data + 16B pad)
#define TILE_BY (128 * LDBY)        // 10240 B : 128x32 fp16 tile
#define STAGE_B (3 * TILE_BY)       // Ah, Al, B = 30720
#define NSTAGE 3
#define SMEM_BYTES (NSTAGE * STAGE_B)   // 92160 per CTA; x2 CTAs = 184320

// ---------------------------------------------------------------------------
// Scratch (__device__ globals; allocation-free rule)
// ---------------------------------------------------------------------------
__device__ __align__(16) __half g_x_hi[BB*SS*DD], g_x_lo[BB*SS*DD];
__device__ __align__(16) __half g_w[3][DD*DD];                    // W single fp16
__device__ __align__(16) __half g_q_hi[BB*SS*DD], g_q_lo[BB*SS*DD];
__device__ __align__(16) __half g_k[BB*SS*DD];                    // K single
__device__ __align__(16) __half g_vT[BB*DD*SS];                   // V^T single [b][d][s]
__device__ __align__(16) float  g_p[(size_t)BB*SS*SS];
__device__ __align__(16) __half g_ph[BB*SS*SS], g_pl[BB*SS*SS];   // P split

// ---------------------------------------------------------------------------
// PTX primitives
// ---------------------------------------------------------------------------
__device__ __forceinline__ void mma_f16(float* d, const uint32_t* a, const uint32_t* b) {
    asm volatile(
        "mma.sync.aligned.m16n8k16.row.col.f32.f16.f16.f32 "
        "{%0,%1,%2,%3}, {%4,%5,%6,%7}, {%8,%9}, {%0,%1,%2,%3};"
        : "+f"(d[0]), "+f"(d[1]), "+f"(d[2]), "+f"(d[3])
        : "r"(a[0]), "r"(a[1]), "r"(a[2]), "r"(a[3]), "r"(b[0]), "r"(b[1]));
}
#define LDSM4(r0, r1, r2, r3, addr) \
    asm volatile("ldmatrix.sync.aligned.m8n8.x4.shared.b16 {%0,%1,%2,%3}, [%4];" \
                 : "=r"(r0), "=r"(r1), "=r"(r2), "=r"(r3) : "r"(addr))
#define CP_ASYNC16(dst, src) \
    asm volatile("cp.async.cg.shared.global [%0], [%1], 16;" :: "r"(dst), "l"(src))
#define CP_COMMIT() asm volatile("cp.async.commit_group;" ::: "memory")
#define CP_WAIT2()  asm volatile("cp.async.wait_group 2;" ::: "memory")

// ---------------------------------------------------------------------------
// cp.async: one 128x32 fp16 tile (K-major, row stride ld elems). 128 threads.
// ---------------------------------------------------------------------------
__device__ __forceinline__ void g2s_tile(uint32_t dst, const __half* __restrict__ g,
                                         size_t ld, int k0, int tid) {
#pragma unroll
    for (int i = 0; i < 4; i++) {
        int slot = tid + (i << 7);      // 0..511
        int row = slot >> 2;            // 0..127
        int c = slot & 3;
        CP_ASYNC16(dst + row * LDBY + c * 16, g + (size_t)row * ld + k0 + c * 8);
    }
}
__device__ __forceinline__ void load_stage(uint32_t st,
    const __half* Ah, const __half* Al, const __half* B,
    size_t lda, size_t ldb, int k0, int tid) {
    g2s_tile(st,              Ah, lda, k0, tid);
    g2s_tile(st + TILE_BY,    Al, lda, k0, tid);
    g2s_tile(st + 2*TILE_BY,  B,  ldb, k0, tid);
}

// ---------------------------------------------------------------------------
// Mainloop: acc[4][8][4] += (Ah + Al)[128,K] . B[128,K]^T   (2-term fp16)
// 128 threads, 4 warps 2x2, warp tile 64x64, 3-stage cp.async pipeline.
// ---------------------------------------------------------------------------
__device__ __forceinline__ void mma_mainloop(
    const __half* __restrict__ Ah, const __half* __restrict__ Al,
    const __half* __restrict__ B,
    size_t lda, size_t ldb, int nch, uint32_t smem, float acc[4][8][4]) {

    const int tid = threadIdx.x;
    const int lane = tid & 31, wid = tid >> 5;
    const int wm = wid >> 1, wn = wid & 1;

    const uint32_t a_off = (uint32_t)(wm * 64 + (lane & 15)) * LDBY + ((lane & 16) ? 16u : 0u);
    const uint32_t b_off = (uint32_t)(wn * 64 + (lane & 7) + ((lane & 16) ? 8 : 0)) * LDBY
                         + ((lane & 8) ? 16u : 0u);

    load_stage(smem, Ah, Al, B, lda, ldb, 0, tid);
    CP_COMMIT();
    if (nch > 1) load_stage(smem + STAGE_B, Ah, Al, B, lda, ldb, 32, tid);
    CP_COMMIT();

    int sidx = 0;
    for (int c = 0; c < nch; c++) {
        if (c + 2 < nch) {
            int s2 = sidx + 2; if (s2 >= NSTAGE) s2 -= NSTAGE;
            load_stage(smem + s2 * STAGE_B, Ah, Al, B, lda, ldb, (c + 2) * 32, tid);
        }
        CP_COMMIT();
        CP_WAIT2();
        __syncthreads();

        const uint32_t st = smem + sidx * STAGE_B;
#pragma unroll
        for (int ks = 0; ks < 2; ks++) {
            const uint32_t ka = st + a_off + ks * 32;
            const uint32_t kb = st + 2 * TILE_BY + b_off + ks * 32;
            uint32_t ah[4][4], bb[8][2];
#pragma unroll
            for (int fm = 0; fm < 4; fm++)
                LDSM4(ah[fm][0], ah[fm][1], ah[fm][2], ah[fm][3], ka + fm * 16 * LDBY);
#pragma unroll
            for (int p = 0; p < 4; p++)
                LDSM4(bb[2*p][0], bb[2*p][1], bb[2*p+1][0], bb[2*p+1][1], kb + p * 16 * LDBY);

            // term 1: Ah x B
#pragma unroll
            for (int fm = 0; fm < 4; fm++)
#pragma unroll
                for (int fn = 0; fn < 8; fn++) mma_f16(acc[fm][fn], ah[fm], bb[fn]);
            // term 2: Al x B (reload a frags)
#pragma unroll
            for (int fm = 0; fm < 4; fm++)
                LDSM4(ah[fm][0], ah[fm][1], ah[fm][2], ah[fm][3],
                      ka + TILE_BY + fm * 16 * LDBY);
#pragma unroll
            for (int fm = 0; fm < 4; fm++)
#pragma unroll
                for (int fn = 0; fn < 8; fn++) mma_f16(acc[fm][fn], ah[fm], bb[fn]);
        }
        __syncthreads();
        if (++sidx == NSTAGE) sidx = 0;
    }
}

#define ZERO_ACC(acc) \
    do { _Pragma("unroll") for (int i = 0; i < 4; i++) \
         _Pragma("unroll") for (int j = 0; j < 8; j++) \
         _Pragma("unroll") for (int r = 0; r < 4; r++) (acc)[i][j][r] = 0.0f; } while (0)

// ---------------------------------------------------------------------------
// Kernel 0: x -> (hi, lo) fp16 split; W -> single fp16
// ---------------------------------------------------------------------------
__global__ __launch_bounds__(256) void split_all(
    const float* __restrict__ x, const float* __restrict__ wq,
    const float* __restrict__ wk, const float* __restrict__ wv) {
    const int which = blockIdx.y;
    if (which == 0) {
        for (int i = blockIdx.x * 256 + threadIdx.x; i < BB*SS*DD; i += gridDim.x * 256) {
            float f = x[i];
            __half h = __float2half(f);
            g_x_hi[i] = h;
            g_x_lo[i] = __float2half(f - __half2float(h));
        }
    } else {
        const float* src = (which == 1) ? wq : (which == 2) ? wk : wv;
        __half* dst = g_w[which - 1];
        for (int i = blockIdx.x * 256 + threadIdx.x; i < DD*DD; i += gridDim.x * 256)
            dst[i] = __float2half(src[i]);
    }
}

// ---------------------------------------------------------------------------
// Kernel 1: QKV.  z=0 -> Q(split), z=1 -> K(single), z=2 -> V^T(single)
// ---------------------------------------------------------------------------
__global__ __launch_bounds__(128, 2) void qkv_mma() {
    extern __shared__ char smraw[];
    const uint32_t smem = (uint32_t)__cvta_generic_to_shared(smraw);
    const int z = blockIdx.z;
    const int m0 = blockIdx.y * 128;
    const int n0 = blockIdx.x * 128;

    float acc[4][8][4];
    ZERO_ACC(acc);

    mma_mainloop(g_x_hi + (size_t)m0 * DD, g_x_lo + (size_t)m0 * DD,
                 g_w[z] + (size_t)n0 * DD, DD, DD, DD / 32, smem, acc);

    const int lane = threadIdx.x & 31, wid = threadIdx.x >> 5;
    const int wm = wid >> 1, wn = wid & 1;
    const int g = lane >> 2, tg = lane & 3;

#pragma unroll
    for (int fm = 0; fm < 4; fm++)
#pragma unroll
        for (int fn = 0; fn < 8; fn++) {
            const int n = n0 + wn * 64 + fn * 8 + tg * 2;
#pragma unroll
            for (int half = 0; half < 2; half++) {
                const int m = m0 + wm * 64 + fm * 16 + g + half * 8;
                float f0 = acc[fm][fn][half * 2], f1 = acc[fm][fn][half * 2 + 1];
                if (z == 0) {
                    __half h0 = __float2half(f0), h1 = __float2half(f1);
                    __half2 h2; h2.x = h0; h2.y = h1;
                    __half2 l2;
                    l2.x = __float2half(f0 - __half2float(h0));
                    l2.y = __float2half(f1 - __half2float(h1));
                    *(__half2*)(g_q_hi + (size_t)m * DD + n) = h2;
                    *(__half2*)(g_q_lo + (size_t)m * DD + n) = l2;
                } else if (z == 1) {
                    __half2 h2; h2.x = __float2half(f0); h2.y = __float2half(f1);
                    *(__half2*)(g_k + (size_t)m * DD + n) = h2;
                } else {
                    const int b = m >> 11, ml = m & (SS - 1);
                    const size_t vb = (size_t)b * DD * SS;
                    g_vT[vb + (size_t)n * SS + ml] = __float2half(f0);
                    g_vT[vb + (size_t)(n + 1) * SS + ml] = __float2half(f1);
                }
            }
        }
}

// ---------------------------------------------------------------------------
// Kernel 2: causal scores (lower-triangular 128x128 tiles; 136 per batch)
// ---------------------------------------------------------------------------
__global__ __launch_bounds__(128, 2) void scores_mma() {
    extern __shared__ char smraw[];
    const uint32_t smem = (uint32_t)__cvta_generic_to_shared(smraw);
    const int t = blockIdx.x;
    int it = (int)floorf((sqrtf(8.0f * (float)t + 1.0f) - 1.0f) * 0.5f);
    while ((it + 1) * (it + 2) / 2 <= t) ++it;
    while (it * (it + 1) / 2 > t) --it;
    const int jt = t - it * (it + 1) / 2;
    const int b = blockIdx.y;
    const int m0 = it * 128, n0 = jt * 128;

    float acc[4][8][4];
    ZERO_ACC(acc);

    const size_t ao = ((size_t)b * SS + m0) * DD;
    const size_t bo = ((size_t)b * SS + n0) * DD;
    mma_mainloop(g_q_hi + ao, g_q_lo + ao, g_k + bo, DD, DD, DD / 32, smem, acc);

    const int lane = threadIdx.x & 31, wid = threadIdx.x >> 5;
    const int wm = wid >> 1, wn = wid & 1;
    const int g = lane >> 2, tg = lane & 3;
    float* C = g_p + (size_t)b * SS * SS;
    const float alpha = 1.0f / 32.0f;

#pragma unroll
    for (int fm = 0; fm < 4; fm++)
#pragma unroll
        for (int fn = 0; fn < 8; fn++) {
            const int n = n0 + wn * 64 + fn * 8 + tg * 2;
#pragma unroll
            for (int half = 0; half < 2; half++) {
                const int m = m0 + wm * 64 + fm * 16 + g + half * 8;
                float2 v;
                v.x = acc[fm][fn][half * 2] * alpha;
                v.y = acc[fm][fn][half * 2 + 1] * alpha;
                *(float2*)(C + (size_t)m * SS + n) = v;
            }
        }
}

// ---------------------------------------------------------------------------
// Kernel 3: causal row softmax; emits split-fp16 P, zero-filled to 128 edge
// ---------------------------------------------------------------------------
__global__ __launch_bounds__(256) void softmax_rows() {
    const int i = blockIdx.x, b = blockIdx.y;
    const size_t rowoff = ((size_t)b * SS + i) * SS;
    float* row = g_p + rowoff;
    const int len = i + 1;
    const int tid = threadIdx.x, lane = tid & 31, wid = tid >> 5;

    __shared__ float red[8];
    __shared__ float s_max, s_sum;

    float m = -1e30f;
    for (int j = tid; j < len; j += 256) m = fmaxf(m, row[j]);
#pragma unroll
    for (int o = 16; o; o >>= 1) m = fmaxf(m, __shfl_xor_sync(0xffffffffu, m, o));
    if (lane == 0) red[wid] = m;
    __syncthreads();
    if (tid < 32) {
        float v = (tid < 8) ? red[tid] : -1e30f;
#pragma unroll
        for (int o = 4; o; o >>= 1) v = fmaxf(v, __shfl_xor_sync(0xffffffffu, v, o));
        if (tid == 0) s_max = v;
    }
    __syncthreads();
    m = s_max;

    float s = 0.0f;
    for (int j = tid; j < len; j += 256) {
        float e = __expf(row[j] - m);
        row[j] = e;
        s += e;
    }
#pragma unroll
    for (int o = 16; o; o >>= 1) s += __shfl_xor_sync(0xffffffffu, s, o);
    __syncthreads();
    if (lane == 0) red[wid] = s;
    __syncthreads();
    if (tid < 32) {
        float v = (tid < 8) ? red[tid] : 0.0f;
#pragma unroll
        for (int o = 4; o; o >>= 1) v += __shfl_xor_sync(0xffffffffu, v, o);
        if (tid == 0) s_sum = v;
    }
    __syncthreads();
    const float inv = 1.0f / s_sum;

    __half* ph = g_ph + rowoff;
    __half* pl = g_pl + rowoff;
    for (int j = tid; j < len; j += 256) {
        float p = row[j] * inv;
        __half h = __float2half(p);
        ph[j] = h;
        pl[j] = __float2half(p - __half2float(h));
    }
    const int tend = ((i >> 7) + 1) << 7;   // ceil to 128 (pv M-tile)
    const __half z = __float2half(0.0f);
    for (int j = len + tid; j < tend; j += 256) { ph[j] = z; pl[j] = z; }
}

// ---------------------------------------------------------------------------
// Kernel 4: O = P @ V.  A = split P (K-major); B = V^T single (K-major).
// Longest row-tiles scheduled first.
// ---------------------------------------------------------------------------
__global__ __launch_bounds__(128, 2) void pv_mma(float* __restrict__ out) {
    extern __shared__ char smraw[];
    const uint32_t smem = (uint32_t)__cvta_generic_to_shared(smraw);
    const int b = blockIdx.z;
    const int it = (SS / 128 - 1) - blockIdx.y;   // 15..0, big tiles first
    const int m0 = it * 128;
    const int n0 = blockIdx.x * 128;
    const int nch = (it + 1) * 4;                 // kend = (it+1)*128

    float acc[4][8][4];
    ZERO_ACC(acc);

    const size_t ao = ((size_t)b * SS + m0) * SS;
    const size_t bo = (size_t)b * DD * SS + (size_t)n0 * SS;
    mma_mainloop(g_ph + ao, g_pl + ao, g_vT + bo, SS, SS, nch, smem, acc);

    const int lane = threadIdx.x & 31, wid = threadIdx.x >> 5;
    const int wm = wid >> 1, wn = wid & 1;
    const int g = lane >> 2, tg = lane & 3;
    float* C = out + (size_t)b * SS * DD;

#pragma unroll
    for (int fm = 0; fm < 4; fm++)
#pragma unroll
        for (int fn = 0; fn < 8; fn++) {
            const int n = n0 + wn * 64 + fn * 8 + tg * 2;
#pragma unroll
            for (int half = 0; half < 2; half++) {
                const int m = m0 + wm * 64 + fm * 16 + g + half * 8;
                float2 v;
                v.x = acc[fm][fn][half * 2];
                v.y = acc[fm][fn][half * 2 + 1];
                *(float2*)(C + (size_t)m * DD + n) = v;
            }
        }
}

// ---------------------------------------------------------------------------
extern "C" void kernel_launch(void* const* d_in, const int* in_sizes, int n_in,
                              void* d_out, int out_size) {
    const float* x  = (const float*)d_in[0];
    const float* wq = (const float*)d_in[1];
    const float* wk = (const float*)d_in[2];
    const float* wv = (const float*)d_in[3];
    float* out = (float*)d_out;
    (void)in_sizes; (void)n_in; (void)out_size;

    static bool attr_done = false;
    if (!attr_done) {
        cudaFuncSetAttribute(qkv_mma,    cudaFuncAttributeMaxDynamicSharedMemorySize, SMEM_BYTES);
        cudaFuncSetAttribute(scores_mma, cudaFuncAttributeMaxDynamicSharedMemorySize, SMEM_BYTES);
        cudaFuncSetAttribute(pv_mma,     cudaFuncAttributeMaxDynamicSharedMemorySize, SMEM_BYTES);
        attr_done = true;
    }

    // 0) fp16 split of x; fp16 W
    split_all<<<dim3(1024, 4), 256>>>(x, wq, wk, wv);

    // 1) Q(split), K, V^T projections
    qkv_mma<<<dim3(DD / 128, (BB * SS) / 128, 3), 128, SMEM_BYTES>>>();

    // 2) causal scores (lower-triangular tiles only)
    const int ntri = (SS / 128) * (SS / 128 + 1) / 2;   // 136
    scores_mma<<<dim3(ntri, BB), 128, SMEM_BYTES>>>();

    // 3) softmax -> split-fp16 P
    softmax_rows<<<dim3(SS, BB), 256>>>();

    // 4) O = P @ V
    pv_mma<<<dim3(DD / 128, SS / 128, BB), 128, SMEM_BYTES>>>(out);
}

// round 7
// speedup vs baseline: 1.9746x; 1.2792x over previous
#include <cuda_runtime.h>
#include <cuda_fp16.h>
#include <cstdint>
#include <math.h>

#define BB 4
#define SS 2048
#define DD 1024

#define LDBY 80                     // smem row stride bytes (64B data + 16B pad)
#define TILE_BY (128 * LDBY)        // 10240 B : 128x32 fp16 tile
#define NSTAGE 3
#define SMEM_Q (NSTAGE * 3 * TILE_BY)   // qkv: Ah, Al, B per stage   = 92160
#define SMEM_S (NSTAGE * 2 * TILE_BY)   // scores/pv: A, B per stage  = 61440

// ---------------------------------------------------------------------------
// Scratch (__device__ globals; allocation-free rule)
// ---------------------------------------------------------------------------
__device__ __align__(16) __half g_x_hi[BB*SS*DD], g_x_lo[BB*SS*DD];
__device__ __align__(16) __half g_w[3][DD*DD];      // W single fp16
__device__ __align__(16) __half g_q[BB*SS*DD];      // Q single
__device__ __align__(16) __half g_k[BB*SS*DD];      // K single
__device__ __align__(16) __half g_vT[BB*DD*SS];     // V^T single [b][d][s]
__device__ __align__(16) float  g_p[(size_t)BB*SS*SS];
__device__ __align__(16) __half g_ph[BB*SS*SS];     // P single

// ---------------------------------------------------------------------------
// PTX primitives
// ---------------------------------------------------------------------------
__device__ __forceinline__ void mma_f16(float* d, const uint32_t* a, const uint32_t* b) {
    asm volatile(
        "mma.sync.aligned.m16n8k16.row.col.f32.f16.f16.f32 "
        "{%0,%1,%2,%3}, {%4,%5,%6,%7}, {%8,%9}, {%0,%1,%2,%3};"
        : "+f"(d[0]), "+f"(d[1]), "+f"(d[2]), "+f"(d[3])
        : "r"(a[0]), "r"(a[1]), "r"(a[2]), "r"(a[3]), "r"(b[0]), "r"(b[1]));
}
#define LDSM4(r0, r1, r2, r3, addr) \
    asm volatile("ldmatrix.sync.aligned.m8n8.x4.shared.b16 {%0,%1,%2,%3}, [%4];" \
                 : "=r"(r0), "=r"(r1), "=r"(r2), "=r"(r3) : "r"(addr))
#define CP_ASYNC16(dst, src) \
    asm volatile("cp.async.cg.shared.global [%0], [%1], 16;" :: "r"(dst), "l"(src))
#define CP_COMMIT() asm volatile("cp.async.commit_group;" ::: "memory")
#define CP_WAIT2()  asm volatile("cp.async.wait_group 2;" ::: "memory")

// ---------------------------------------------------------------------------
// cp.async: one 128x32 fp16 tile (K-major, row stride ld elems). 128 threads.
// ---------------------------------------------------------------------------
__device__ __forceinline__ void g2s_tile(uint32_t dst, const __half* __restrict__ g,
                                         size_t ld, int k0, int tid) {
#pragma unroll
    for (int i = 0; i < 4; i++) {
        int slot = tid + (i << 7);      // 0..511
        int row = slot >> 2;            // 0..127
        int c = slot & 3;
        CP_ASYNC16(dst + row * LDBY + c * 16, g + (size_t)row * ld + k0 + c * 8);
    }
}

// ---------------------------------------------------------------------------
// Mainloop (templated on number of A terms):
//   TERMS=2: acc += (Ah + Al) . B^T      (qkv)
//   TERMS=1: acc += Ah . B^T             (scores, pv)
// 128 threads, 4 warps 2x2, warp tile 64x64, 3-stage cp.async pipeline.
// ---------------------------------------------------------------------------
template <int TERMS>
__device__ __forceinline__ void mma_mainloop(
    const __half* __restrict__ Ah, const __half* __restrict__ Al,
    const __half* __restrict__ B,
    size_t lda, size_t ldb, int nch, uint32_t smem, float acc[4][8][4]) {

    const uint32_t STG = (TERMS + 1) * TILE_BY;
    const int tid = threadIdx.x;
    const int lane = tid & 31, wid = tid >> 5;
    const int wm = wid >> 1, wn = wid & 1;

    const uint32_t a_off = (uint32_t)(wm * 64 + (lane & 15)) * LDBY + ((lane & 16) ? 16u : 0u);
    const uint32_t b_off = (uint32_t)(wn * 64 + (lane & 7) + ((lane & 16) ? 8 : 0)) * LDBY
                         + ((lane & 8) ? 16u : 0u);

    // prologue: stages 0, 1
#pragma unroll
    for (int s = 0; s < 2; s++) {
        if (s < nch) {
            uint32_t st = smem + s * STG;
            g2s_tile(st, Ah, lda, s * 32, tid);
            if (TERMS == 2) g2s_tile(st + TILE_BY, Al, lda, s * 32, tid);
            g2s_tile(st + TERMS * TILE_BY, B, ldb, s * 32, tid);
        }
        CP_COMMIT();
    }

    int sidx = 0;
    for (int c = 0; c < nch; c++) {
        if (c + 2 < nch) {
            int s2 = sidx + 2; if (s2 >= NSTAGE) s2 -= NSTAGE;
            uint32_t st = smem + s2 * STG;
            const int k0 = (c + 2) * 32;
            g2s_tile(st, Ah, lda, k0, tid);
            if (TERMS == 2) g2s_tile(st + TILE_BY, Al, lda, k0, tid);
            g2s_tile(st + TERMS * TILE_BY, B, ldb, k0, tid);
        }
        CP_COMMIT();
        CP_WAIT2();
        __syncthreads();

        const uint32_t st = smem + sidx * STG;
#pragma unroll
        for (int ks = 0; ks < 2; ks++) {
            const uint32_t ka = st + a_off + ks * 32;
            const uint32_t kb = st + TERMS * TILE_BY + b_off + ks * 32;
            uint32_t ah[4][4], bb[8][2];
#pragma unroll
            for (int fm = 0; fm < 4; fm++)
                LDSM4(ah[fm][0], ah[fm][1], ah[fm][2], ah[fm][3], ka + fm * 16 * LDBY);
#pragma unroll
            for (int p = 0; p < 4; p++)
                LDSM4(bb[2*p][0], bb[2*p][1], bb[2*p+1][0], bb[2*p+1][1], kb + p * 16 * LDBY);

            // term 1: Ah x B
#pragma unroll
            for (int fm = 0; fm < 4; fm++)
#pragma unroll
                for (int fn = 0; fn < 8; fn++) mma_f16(acc[fm][fn], ah[fm], bb[fn]);
            if (TERMS == 2) {
                // term 2: Al x B (reload a frags)
#pragma unroll
                for (int fm = 0; fm < 4; fm++)
                    LDSM4(ah[fm][0], ah[fm][1], ah[fm][2], ah[fm][3],
                          ka + TILE_BY + fm * 16 * LDBY);
#pragma unroll
                for (int fm = 0; fm < 4; fm++)
#pragma unroll
                    for (int fn = 0; fn < 8; fn++) mma_f16(acc[fm][fn], ah[fm], bb[fn]);
            }
        }
        __syncthreads();
        if (++sidx == NSTAGE) sidx = 0;
    }
}

#define ZERO_ACC(acc) \
    do { _Pragma("unroll") for (int i = 0; i < 4; i++) \
         _Pragma("unroll") for (int j = 0; j < 8; j++) \
         _Pragma("unroll") for (int r = 0; r < 4; r++) (acc)[i][j][r] = 0.0f; } while (0)

// ---------------------------------------------------------------------------
// Kernel 0: x -> (hi, lo) fp16 split; W -> single fp16
// ---------------------------------------------------------------------------
__global__ __launch_bounds__(256) void split_all(
    const float* __restrict__ x, const float* __restrict__ wq,
    const float* __restrict__ wk, const float* __restrict__ wv) {
    const int which = blockIdx.y;
    if (which == 0) {
        for (int i = blockIdx.x * 256 + threadIdx.x; i < BB*SS*DD; i += gridDim.x * 256) {
            float f = x[i];
            __half h = __float2half(f);
            g_x_hi[i] = h;
            g_x_lo[i] = __float2half(f - __half2float(h));
        }
    } else {
        const float* src = (which == 1) ? wq : (which == 2) ? wk : wv;
        __half* dst = g_w[which - 1];
        for (int i = blockIdx.x * 256 + threadIdx.x; i < DD*DD; i += gridDim.x * 256)
            dst[i] = __float2half(src[i]);
    }
}

// ---------------------------------------------------------------------------
// Kernel 1: QKV (x split, 2-term).  z=0 -> Q, z=1 -> K, z=2 -> V^T (all single)
// ---------------------------------------------------------------------------
__global__ __launch_bounds__(128, 2) void qkv_mma() {
    extern __shared__ char smraw[];
    const uint32_t smem = (uint32_t)__cvta_generic_to_shared(smraw);
    const int z = blockIdx.z;
    const int m0 = blockIdx.y * 128;
    const int n0 = blockIdx.x * 128;

    float acc[4][8][4];
    ZERO_ACC(acc);

    mma_mainloop<2>(g_x_hi + (size_t)m0 * DD, g_x_lo + (size_t)m0 * DD,
                    g_w[z] + (size_t)n0 * DD, DD, DD, DD / 32, smem, acc);

    const int lane = threadIdx.x & 31, wid = threadIdx.x >> 5;
    const int wm = wid >> 1, wn = wid & 1;
    const int g = lane >> 2, tg = lane & 3;

#pragma unroll
    for (int fm = 0; fm < 4; fm++)
#pragma unroll
        for (int fn = 0; fn < 8; fn++) {
            const int n = n0 + wn * 64 + fn * 8 + tg * 2;
#pragma unroll
            for (int half = 0; half < 2; half++) {
                const int m = m0 + wm * 64 + fm * 16 + g + half * 8;
                float f0 = acc[fm][fn][half * 2], f1 = acc[fm][fn][half * 2 + 1];
                if (z < 2) {
                    __half* D = z ? g_k : g_q;
                    __half2 h2; h2.x = __float2half(f0); h2.y = __float2half(f1);
                    *(__half2*)(D + (size_t)m * DD + n) = h2;
                } else {
                    const int b = m >> 11, ml = m & (SS - 1);
                    const size_t vb = (size_t)b * DD * SS;
                    g_vT[vb + (size_t)n * SS + ml] = __float2half(f0);
                    g_vT[vb + (size_t)(n + 1) * SS + ml] = __float2half(f1);
                }
            }
        }
}

// ---------------------------------------------------------------------------
// Kernel 2: causal scores, single-term (lower-triangular tiles; 136 per batch)
// ---------------------------------------------------------------------------
__global__ __launch_bounds__(128, 2) void scores_mma() {
    extern __shared__ char smraw[];
    const uint32_t smem = (uint32_t)__cvta_generic_to_shared(smraw);
    const int t = blockIdx.x;
    int it = (int)floorf((sqrtf(8.0f * (float)t + 1.0f) - 1.0f) * 0.5f);
    while ((it + 1) * (it + 2) / 2 <= t) ++it;
    while (it * (it + 1) / 2 > t) --it;
    const int jt = t - it * (it + 1) / 2;
    const int b = blockIdx.y;
    const int m0 = it * 128, n0 = jt * 128;

    float acc[4][8][4];
    ZERO_ACC(acc);

    const size_t ao = ((size_t)b * SS + m0) * DD;
    const size_t bo = ((size_t)b * SS + n0) * DD;
    mma_mainloop<1>(g_q + ao, nullptr, g_k + bo, DD, DD, DD / 32, smem, acc);

    const int lane = threadIdx.x & 31, wid = threadIdx.x >> 5;
    const int wm = wid >> 1, wn = wid & 1;
    const int g = lane >> 2, tg = lane & 3;
    float* C = g_p + (size_t)b * SS * SS;
    const float alpha = 1.0f / 32.0f;

#pragma unroll
    for (int fm = 0; fm < 4; fm++)
#pragma unroll
        for (int fn = 0; fn < 8; fn++) {
            const int n = n0 + wn * 64 + fn * 8 + tg * 2;
#pragma unroll
            for (int half = 0; half < 2; half++) {
                const int m = m0 + wm * 64 + fm * 16 + g + half * 8;
                float2 v;
                v.x = acc[fm][fn][half * 2] * alpha;
                v.y = acc[fm][fn][half * 2 + 1] * alpha;
                *(float2*)(C + (size_t)m * SS + n) = v;
            }
        }
}

// ---------------------------------------------------------------------------
// Kernel 3: causal row softmax; emits single-fp16 P, zero-filled to 128 edge
// ---------------------------------------------------------------------------
__global__ __launch_bounds__(256) void softmax_rows() {
    const int i = blockIdx.x, b = blockIdx.y;
    const size_t rowoff = ((size_t)b * SS + i) * SS;
    float* row = g_p + rowoff;
    const int len = i + 1;
    const int tid = threadIdx.x, lane = tid & 31, wid = tid >> 5;

    __shared__ float red[8];
    __shared__ float s_max, s_sum;

    float m = -1e30f;
    for (int j = tid; j < len; j += 256) m = fmaxf(m, row[j]);
#pragma unroll
    for (int o = 16; o; o >>= 1) m = fmaxf(m, __shfl_xor_sync(0xffffffffu, m, o));
    if (lane == 0) red[wid] = m;
    __syncthreads();
    if (tid < 32) {
        float v = (tid < 8) ? red[tid] : -1e30f;
#pragma unroll
        for (int o = 4; o; o >>= 1) v = fmaxf(v, __shfl_xor_sync(0xffffffffu, v, o));
        if (tid == 0) s_max = v;
    }
    __syncthreads();
    m = s_max;

    float s = 0.0f;
    for (int j = tid; j < len; j += 256) {
        float e = __expf(row[j] - m);
        row[j] = e;
        s += e;
    }
#pragma unroll
    for (int o = 16; o; o >>= 1) s += __shfl_xor_sync(0xffffffffu, s, o);
    __syncthreads();
    if (lane == 0) red[wid] = s;
    __syncthreads();
    if (tid < 32) {
        float v = (tid < 8) ? red[tid] : 0.0f;
#pragma unroll
        for (int o = 4; o; o >>= 1) v += __shfl_xor_sync(0xffffffffu, v, o);
        if (tid == 0) s_sum = v;
    }
    __syncthreads();
    const float inv = 1.0f / s_sum;

    __half* ph = g_ph + rowoff;
    for (int j = tid; j < len; j += 256)
        ph[j] = __float2half(row[j] * inv);
    const int tend = ((i >> 7) + 1) << 7;   // ceil to 128 (pv M-tile)
    const __half z = __float2half(0.0f);
    for (int j = len + tid; j < tend; j += 256) ph[j] = z;
}

// ---------------------------------------------------------------------------
// Kernel 4: O = P @ V, single-term.  A = P (K-major); B = V^T (K-major).
// Longest row-tiles scheduled first.
// ---------------------------------------------------------------------------
__global__ __launch_bounds__(128, 2) void pv_mma(float* __restrict__ out) {
    extern __shared__ char smraw[];
    const uint32_t smem = (uint32_t)__cvta_generic_to_shared(smraw);
    const int b = blockIdx.z;
    const int it = (SS / 128 - 1) - blockIdx.y;   // 15..0, big tiles first
    const int m0 = it * 128;
    const int n0 = blockIdx.x * 128;
    const int nch = (it + 1) * 4;                 // kend = (it+1)*128

    float acc[4][8][4];
    ZERO_ACC(acc);

    const size_t ao = ((size_t)b * SS + m0) * SS;
    const size_t bo = (size_t)b * DD * SS + (size_t)n0 * SS;
    mma_mainloop<1>(g_ph + ao, nullptr, g_vT + bo, SS, SS, nch, smem, acc);

    const int lane = threadIdx.x & 31, wid = threadIdx.x >> 5;
    const int wm = wid >> 1, wn = wid & 1;
    const int g = lane >> 2, tg = lane & 3;
    float* C = out + (size_t)b * SS * DD;

#pragma unroll
    for (int fm = 0; fm < 4; fm++)
#pragma unroll
        for (int fn = 0; fn < 8; fn++) {
            const int n = n0 + wn * 64 + fn * 8 + tg * 2;
#pragma unroll
            for (int half = 0; half < 2; half++) {
                const int m = m0 + wm * 64 + fm * 16 + g + half * 8;
                float2 v;
                v.x = acc[fm][fn][half * 2];
                v.y = acc[fm][fn][half * 2 + 1];
                *(float2*)(C + (size_t)m * DD + n) = v;
            }
        }
}

// ---------------------------------------------------------------------------
extern "C" void kernel_launch(void* const* d_in, const int* in_sizes, int n_in,
                              void* d_out, int out_size) {
    const float* x  = (const float*)d_in[0];
    const float* wq = (const float*)d_in[1];
    const float* wk = (const float*)d_in[2];
    const float* wv = (const float*)d_in[3];
    float* out = (float*)d_out;
    (void)in_sizes; (void)n_in; (void)out_size;

    static bool attr_done = false;
    if (!attr_done) {
        cudaFuncSetAttribute(qkv_mma,    cudaFuncAttributeMaxDynamicSharedMemorySize, SMEM_Q);
        cudaFuncSetAttribute(scores_mma, cudaFuncAttributeMaxDynamicSharedMemorySize, SMEM_S);
        cudaFuncSetAttribute(pv_mma,     cudaFuncAttributeMaxDynamicSharedMemorySize, SMEM_S);
        attr_done = true;
    }

    // 0) fp16 split of x; fp16 W
    split_all<<<dim3(1024, 4), 256>>>(x, wq, wk, wv);

    // 1) Q, K, V^T projections (x split, 2-term)
    qkv_mma<<<dim3(DD / 128, (BB * SS) / 128, 3), 128, SMEM_Q>>>();

    // 2) causal scores (single-term, lower-triangular tiles only)
    const int ntri = (SS / 128) * (SS / 128 + 1) / 2;   // 136
    scores_mma<<<dim3(ntri, BB), 128, SMEM_S>>>();

    // 3) softmax -> single-fp16 P
    softmax_rows<<<dim3(SS, BB), 256>>>();

    // 4) O = P @ V (single-term)
    pv_mma<<<dim3(DD / 128, SS / 128, BB), 128, SMEM_S>>>(out);
}

// round 8
// speedup vs baseline: 2.9069x; 1.4722x over previous
#include <cuda_runtime.h>
#include <cuda_fp16.h>
#include <cstdint>
#include <math.h>

#define BB 4
#define SS 2048
#define DD 1024

#define LDBY 80                     // smem row stride bytes (64B data + 16B pad)
#define TILE_BY (128 * LDBY)        // 10240 B : 128x32 fp16 tile
#define NSTAGE 3
#define STAGE_B (2 * TILE_BY)       // A, B per stage
#define SMEM_BYTES (NSTAGE * STAGE_B)   // 61440 per CTA; 2 CTAs/SM = 122880

// ---------------------------------------------------------------------------
// Scratch (__device__ globals; allocation-free rule)
// ---------------------------------------------------------------------------
__device__ __align__(16) __half g_x[BB*SS*DD];      // x single fp16
__device__ __align__(16) __half g_w[3][DD*DD];      // W single fp16
__device__ __align__(16) __half g_q[BB*SS*DD];      // Q single
__device__ __align__(16) __half g_k[BB*SS*DD];      // K single
__device__ __align__(16) __half g_vT[BB*DD*SS];     // V^T single [b][d][s]
__device__ __align__(16) float  g_p[(size_t)BB*SS*SS];
__device__ __align__(16) __half g_ph[BB*SS*SS];     // P single

// ---------------------------------------------------------------------------
// PTX primitives
// ---------------------------------------------------------------------------
__device__ __forceinline__ void mma_f16(float* d, const uint32_t* a, const uint32_t* b) {
    asm volatile(
        "mma.sync.aligned.m16n8k16.row.col.f32.f16.f16.f32 "
        "{%0,%1,%2,%3}, {%4,%5,%6,%7}, {%8,%9}, {%0,%1,%2,%3};"
        : "+f"(d[0]), "+f"(d[1]), "+f"(d[2]), "+f"(d[3])
        : "r"(a[0]), "r"(a[1]), "r"(a[2]), "r"(a[3]), "r"(b[0]), "r"(b[1]));
}
#define LDSM4(r0, r1, r2, r3, addr) \
    asm volatile("ldmatrix.sync.aligned.m8n8.x4.shared.b16 {%0,%1,%2,%3}, [%4];" \
                 : "=r"(r0), "=r"(r1), "=r"(r2), "=r"(r3) : "r"(addr))
#define CP_ASYNC16(dst, src) \
    asm volatile("cp.async.cg.shared.global [%0], [%1], 16;" :: "r"(dst), "l"(src))
#define CP_COMMIT() asm volatile("cp.async.commit_group;" ::: "memory")
#define CP_WAIT2()  asm volatile("cp.async.wait_group 2;" ::: "memory")

// ---------------------------------------------------------------------------
// cp.async: one 128x32 fp16 tile (K-major, row stride ld elems). 128 threads.
// ---------------------------------------------------------------------------
__device__ __forceinline__ void g2s_tile(uint32_t dst, const __half* __restrict__ g,
                                         size_t ld, int k0, int tid) {
#pragma unroll
    for (int i = 0; i < 4; i++) {
        int slot = tid + (i << 7);      // 0..511
        int row = slot >> 2;            // 0..127
        int c = slot & 3;
        CP_ASYNC16(dst + row * LDBY + c * 16, g + (size_t)row * ld + k0 + c * 8);
    }
}

// ---------------------------------------------------------------------------
// Mainloop: acc[4][8][4] += A[128,K] . B[128,K]^T  (single-term fp16)
// 128 threads, 4 warps 2x2, warp tile 64x64, 3-stage cp.async pipeline.
// ---------------------------------------------------------------------------
__device__ __forceinline__ void mma_mainloop(
    const __half* __restrict__ A, const __half* __restrict__ B,
    size_t lda, size_t ldb, int nch, uint32_t smem, float acc[4][8][4]) {

    const int tid = threadIdx.x;
    const int lane = tid & 31, wid = tid >> 5;
    const int wm = wid >> 1, wn = wid & 1;

    const uint32_t a_off = (uint32_t)(wm * 64 + (lane & 15)) * LDBY + ((lane & 16) ? 16u : 0u);
    const uint32_t b_off = (uint32_t)(wn * 64 + (lane & 7) + ((lane & 16) ? 8 : 0)) * LDBY
                         + ((lane & 8) ? 16u : 0u);

    // prologue: stages 0, 1
#pragma unroll
    for (int s = 0; s < 2; s++) {
        if (s < nch) {
            uint32_t st = smem + s * STAGE_B;
            g2s_tile(st,           A, lda, s * 32, tid);
            g2s_tile(st + TILE_BY, B, ldb, s * 32, tid);
        }
        CP_COMMIT();
    }

    int sidx = 0;
    for (int c = 0; c < nch; c++) {
        if (c + 2 < nch) {
            int s2 = sidx + 2; if (s2 >= NSTAGE) s2 -= NSTAGE;
            uint32_t st = smem + s2 * STAGE_B;
            const int k0 = (c + 2) * 32;
            g2s_tile(st,           A, lda, k0, tid);
            g2s_tile(st + TILE_BY, B, ldb, k0, tid);
        }
        CP_COMMIT();
        CP_WAIT2();
        __syncthreads();

        const uint32_t st = smem + sidx * STAGE_B;
#pragma unroll
        for (int ks = 0; ks < 2; ks++) {
            const uint32_t ka = st + a_off + ks * 32;
            const uint32_t kb = st + TILE_BY + b_off + ks * 32;
            uint32_t ah[4][4], bb[8][2];
#pragma unroll
            for (int fm = 0; fm < 4; fm++)
                LDSM4(ah[fm][0], ah[fm][1], ah[fm][2], ah[fm][3], ka + fm * 16 * LDBY);
#pragma unroll
            for (int p = 0; p < 4; p++)
                LDSM4(bb[2*p][0], bb[2*p][1], bb[2*p+1][0], bb[2*p+1][1], kb + p * 16 * LDBY);
#pragma unroll
            for (int fm = 0; fm < 4; fm++)
#pragma unroll
                for (int fn = 0; fn < 8; fn++) mma_f16(acc[fm][fn], ah[fm], bb[fn]);
        }
        __syncthreads();
        if (++sidx == NSTAGE) sidx = 0;
    }
}

#define ZERO_ACC(acc) \
    do { _Pragma("unroll") for (int i = 0; i < 4; i++) \
         _Pragma("unroll") for (int j = 0; j < 8; j++) \
         _Pragma("unroll") for (int r = 0; r < 4; r++) (acc)[i][j][r] = 0.0f; } while (0)

// ---------------------------------------------------------------------------
// Kernel 0: convert x, Wq, Wk, Wv to fp16
// ---------------------------------------------------------------------------
__global__ __launch_bounds__(256) void convert_all(
    const float* __restrict__ x, const float* __restrict__ wq,
    const float* __restrict__ wk, const float* __restrict__ wv) {
    const int which = blockIdx.y;
    const float* src = (which == 0) ? x : (which == 1) ? wq : (which == 2) ? wk : wv;
    __half* dst = (which == 0) ? g_x : g_w[which - 1];
    const int n = (which == 0) ? BB * SS * DD : DD * DD;
    for (int i = blockIdx.x * 256 + threadIdx.x; i * 2 < n; i += gridDim.x * 256) {
        float2 f = *(const float2*)(src + i * 2);
        __half2 h; h.x = __float2half(f.x); h.y = __float2half(f.y);
        *(__half2*)(dst + i * 2) = h;
    }
}

// ---------------------------------------------------------------------------
// Kernel 1: QKV single-term.  z=0 -> Q, z=1 -> K, z=2 -> V^T
// ---------------------------------------------------------------------------
__global__ __launch_bounds__(128, 2) void qkv_mma() {
    extern __shared__ char smraw[];
    const uint32_t smem = (uint32_t)__cvta_generic_to_shared(smraw);
    const int z = blockIdx.z;
    const int m0 = blockIdx.y * 128;
    const int n0 = blockIdx.x * 128;

    float acc[4][8][4];
    ZERO_ACC(acc);

    mma_mainloop(g_x + (size_t)m0 * DD, g_w[z] + (size_t)n0 * DD,
                 DD, DD, DD / 32, smem, acc);

    const int lane = threadIdx.x & 31, wid = threadIdx.x >> 5;
    const int wm = wid >> 1, wn = wid & 1;
    const int g = lane >> 2, tg = lane & 3;

#pragma unroll
    for (int fm = 0; fm < 4; fm++)
#pragma unroll
        for (int fn = 0; fn < 8; fn++) {
            const int n = n0 + wn * 64 + fn * 8 + tg * 2;
#pragma unroll
            for (int half = 0; half < 2; half++) {
                const int m = m0 + wm * 64 + fm * 16 + g + half * 8;
                float f0 = acc[fm][fn][half * 2], f1 = acc[fm][fn][half * 2 + 1];
                if (z < 2) {
                    __half* D = z ? g_k : g_q;
                    __half2 h2; h2.x = __float2half(f0); h2.y = __float2half(f1);
                    *(__half2*)(D + (size_t)m * DD + n) = h2;
                } else {
                    const int b = m >> 11, ml = m & (SS - 1);
                    const size_t vb = (size_t)b * DD * SS;
                    g_vT[vb + (size_t)n * SS + ml] = __float2half(f0);
                    g_vT[vb + (size_t)(n + 1) * SS + ml] = __float2half(f1);
                }
            }
        }
}

// ---------------------------------------------------------------------------
// Kernel 2: causal scores (lower-triangular 128x128 tiles; 136 per batch)
// ---------------------------------------------------------------------------
__global__ __launch_bounds__(128, 2) void scores_mma() {
    extern __shared__ char smraw[];
    const uint32_t smem = (uint32_t)__cvta_generic_to_shared(smraw);
    const int t = blockIdx.x;
    int it = (int)floorf((sqrtf(8.0f * (float)t + 1.0f) - 1.0f) * 0.5f);
    while ((it + 1) * (it + 2) / 2 <= t) ++it;
    while (it * (it + 1) / 2 > t) --it;
    const int jt = t - it * (it + 1) / 2;
    const int b = blockIdx.y;
    const int m0 = it * 128, n0 = jt * 128;

    float acc[4][8][4];
    ZERO_ACC(acc);

    const size_t ao = ((size_t)b * SS + m0) * DD;
    const size_t bo = ((size_t)b * SS + n0) * DD;
    mma_mainloop(g_q + ao, g_k + bo, DD, DD, DD / 32, smem, acc);

    const int lane = threadIdx.x & 31, wid = threadIdx.x >> 5;
    const int wm = wid >> 1, wn = wid & 1;
    const int g = lane >> 2, tg = lane & 3;
    float* C = g_p + (size_t)b * SS * SS;
    const float alpha = 1.0f / 32.0f;

#pragma unroll
    for (int fm = 0; fm < 4; fm++)
#pragma unroll
        for (int fn = 0; fn < 8; fn++) {
            const int n = n0 + wn * 64 + fn * 8 + tg * 2;
#pragma unroll
            for (int half = 0; half < 2; half++) {
                const int m = m0 + wm * 64 + fm * 16 + g + half * 8;
                float2 v;
                v.x = acc[fm][fn][half * 2] * alpha;
                v.y = acc[fm][fn][half * 2 + 1] * alpha;
                *(float2*)(C + (size_t)m * SS + n) = v;
            }
        }
}

// ---------------------------------------------------------------------------
// Kernel 3: causal row softmax; emits single-fp16 P, zero-filled to 128 edge
// ---------------------------------------------------------------------------
__global__ __launch_bounds__(256) void softmax_rows() {
    const int i = blockIdx.x, b = blockIdx.y;
    const size_t rowoff = ((size_t)b * SS + i) * SS;
    float* row = g_p + rowoff;
    const int len = i + 1;
    const int tid = threadIdx.x, lane = tid & 31, wid = tid >> 5;

    __shared__ float red[8];
    __shared__ float s_max, s_sum;

    float m = -1e30f;
    for (int j = tid; j < len; j += 256) m = fmaxf(m, row[j]);
#pragma unroll
    for (int o = 16; o; o >>= 1) m = fmaxf(m, __shfl_xor_sync(0xffffffffu, m, o));
    if (lane == 0) red[wid] = m;
    __syncthreads();
    if (tid < 32) {
        float v = (tid < 8) ? red[tid] : -1e30f;
#pragma unroll
        for (int o = 4; o; o >>= 1) v = fmaxf(v, __shfl_xor_sync(0xffffffffu, v, o));
        if (tid == 0) s_max = v;
    }
    __syncthreads();
    m = s_max;

    float s = 0.0f;
    for (int j = tid; j < len; j += 256) {
        float e = __expf(row[j] - m);
        row[j] = e;
        s += e;
    }
#pragma unroll
    for (int o = 16; o; o >>= 1) s += __shfl_xor_sync(0xffffffffu, s, o);
    __syncthreads();
    if (lane == 0) red[wid] = s;
    __syncthreads();
    if (tid < 32) {
        float v = (tid < 8) ? red[tid] : 0.0f;
#pragma unroll
        for (int o = 4; o; o >>= 1) v += __shfl_xor_sync(0xffffffffu, v, o);
        if (tid == 0) s_sum = v;
    }
    __syncthreads();
    const float inv = 1.0f / s_sum;

    __half* ph = g_ph + rowoff;
    for (int j = tid; j < len; j += 256)
        ph[j] = __float2half(row[j] * inv);
    const int tend = ((i >> 7) + 1) << 7;   // ceil to 128 (pv M-tile)
    const __half z = __float2half(0.0f);
    for (int j = len + tid; j < tend; j += 256) ph[j] = z;
}

// ---------------------------------------------------------------------------
// Kernel 4: O = P @ V single-term.  Longest row-tiles first.
// ---------------------------------------------------------------------------
__global__ __launch_bounds__(128, 2) void pv_mma(float* __restrict__ out) {
    extern __shared__ char smraw[];
    const uint32_t smem = (uint32_t)__cvta_generic_to_shared(smraw);
    const int b = blockIdx.z;
    const int it = (SS / 128 - 1) - blockIdx.y;   // 15..0, big tiles first
    const int m0 = it * 128;
    const int n0 = blockIdx.x * 128;
    const int nch = (it + 1) * 4;                 // kend = (it+1)*128

    float acc[4][8][4];
    ZERO_ACC(acc);

    const size_t ao = ((size_t)b * SS + m0) * SS;
    const size_t bo = (size_t)b * DD * SS + (size_t)n0 * SS;
    mma_mainloop(g_ph + ao, g_vT + bo, SS, SS, nch, smem, acc);

    const int lane = threadIdx.x & 31, wid = threadIdx.x >> 5;
    const int wm = wid >> 1, wn = wid & 1;
    const int g = lane >> 2, tg = lane & 3;
    float* C = out + (size_t)b * SS * DD;

#pragma unroll
    for (int fm = 0; fm < 4; fm++)
#pragma unroll
        for (int fn = 0; fn < 8; fn++) {
            const int n = n0 + wn * 64 + fn * 8 + tg * 2;
#pragma unroll
            for (int half = 0; half < 2; half++) {
                const int m = m0 + wm * 64 + fm * 16 + g + half * 8;
                float2 v;
                v.x = acc[fm][fn][half * 2];
                v.y = acc[fm][fn][half * 2 + 1];
                *(float2*)(C + (size_t)m * DD + n) = v;
            }
        }
}

// ---------------------------------------------------------------------------
extern "C" void kernel_launch(void* const* d_in, const int* in_sizes, int n_in,
                              void* d_out, int out_size) {
    const float* x  = (const float*)d_in[0];
    const float* wq = (const float*)d_in[1];
    const float* wk = (const float*)d_in[2];
    const float* wv = (const float*)d_in[3];
    float* out = (float*)d_out;
    (void)in_sizes; (void)n_in; (void)out_size;

    static bool attr_done = false;
    if (!attr_done) {
        cudaFuncSetAttribute(qkv_mma,    cudaFuncAttributeMaxDynamicSharedMemorySize, SMEM_BYTES);
        cudaFuncSetAttribute(scores_mma, cudaFuncAttributeMaxDynamicSharedMemorySize, SMEM_BYTES);
        cudaFuncSetAttribute(pv_mma,     cudaFuncAttributeMaxDynamicSharedMemorySize, SMEM_BYTES);
        attr_done = true;
    }

    // 0) convert x, W to fp16
    convert_all<<<dim3(1024, 4), 256>>>(x, wq, wk, wv);

    // 1) Q, K, V^T projections (single-term)
    qkv_mma<<<dim3(DD / 128, (BB * SS) / 128, 3), 128, SMEM_BYTES>>>();

    // 2) causal scores (single-term, lower-triangular tiles only)
    const int ntri = (SS / 128) * (SS / 128 + 1) / 2;   // 136
    scores_mma<<<dim3(ntri, BB), 128, SMEM_BYTES>>>();

    // 3) softmax -> single-fp16 P
    softmax_rows<<<dim3(SS, BB), 256>>>();

    // 4) O = P @ V (single-term)
    pv_mma<<<dim3(DD / 128, SS / 128, BB), 128, SMEM_BYTES>>>(out);
}

// round 9
// speedup vs baseline: 3.2761x; 1.1270x over previous
#include <cuda_runtime.h>
#include <cuda_fp16.h>
#include <cstdint>
#include <math.h>

#define BB 4
#define SS 2048
#define DD 1024

#define LDBY 144                    // smem row stride bytes (128B data + 16B pad)
#define TILE_BY (128 * LDBY)        // 18432 B : 128x64 fp16 tile
#define NSTAGE 3
#define STAGE_B (2 * TILE_BY)       // A, B per stage = 36864
#define SMEM_BYTES (NSTAGE * STAGE_B)   // 110592 per CTA; 2 CTAs/SM = 221184

// ---------------------------------------------------------------------------
// Scratch (__device__ globals; allocation-free rule)
// ---------------------------------------------------------------------------
__device__ __align__(16) __half g_x[BB*SS*DD];
__device__ __align__(16) __half g_w[3][DD*DD];
__device__ __align__(16) __half g_q[BB*SS*DD];
__device__ __align__(16) __half g_k[BB*SS*DD];
__device__ __align__(16) __half g_vT[BB*DD*SS];     // V^T [b][d][s]
__device__ __align__(16) __half g_ph[BB*SS*SS];     // p~ = exp(s/32), causal-masked
__device__ __align__(16) float  g_inv[BB*SS];       // 1 / row sum

// ---------------------------------------------------------------------------
// PTX primitives
// ---------------------------------------------------------------------------
__device__ __forceinline__ void mma_f16(float* d, const uint32_t* a, const uint32_t* b) {
    asm volatile(
        "mma.sync.aligned.m16n8k16.row.col.f32.f16.f16.f32 "
        "{%0,%1,%2,%3}, {%4,%5,%6,%7}, {%8,%9}, {%0,%1,%2,%3};"
        : "+f"(d[0]), "+f"(d[1]), "+f"(d[2]), "+f"(d[3])
        : "r"(a[0]), "r"(a[1]), "r"(a[2]), "r"(a[3]), "r"(b[0]), "r"(b[1]));
}
#define LDSM4(r0, r1, r2, r3, addr) \
    asm volatile("ldmatrix.sync.aligned.m8n8.x4.shared.b16 {%0,%1,%2,%3}, [%4];" \
                 : "=r"(r0), "=r"(r1), "=r"(r2), "=r"(r3) : "r"(addr))
#define CP_ASYNC16(dst, src) \
    asm volatile("cp.async.cg.shared.global [%0], [%1], 16;" :: "r"(dst), "l"(src))
#define CP_COMMIT() asm volatile("cp.async.commit_group;" ::: "memory")
#define CP_WAIT1()  asm volatile("cp.async.wait_group 1;" ::: "memory")

// ---------------------------------------------------------------------------
// cp.async: one 128x64 fp16 tile (K-major, row stride ld elems). 128 threads.
// ---------------------------------------------------------------------------
__device__ __forceinline__ void g2s_tile(uint32_t dst, const __half* __restrict__ g,
                                         size_t ld, int k0, int tid) {
#pragma unroll
    for (int i = 0; i < 8; i++) {
        int slot = tid + (i << 7);      // 0..1023
        int row = slot >> 3;            // 0..127
        int c = slot & 7;               // 16B chunk
        CP_ASYNC16(dst + row * LDBY + c * 16, g + (size_t)row * ld + k0 + c * 8);
    }
}

// ---------------------------------------------------------------------------
// Mainloop: acc[4][8][4] += A[128,K] . B[128,K]^T  (fp16, K-chunk 64)
// 128 threads, 4 warps 2x2, warp tile 64x64, 3-stage cp.async pipeline,
// ONE __syncthreads per chunk (compute-then-prefetch ordering).
// ---------------------------------------------------------------------------
__device__ __forceinline__ void mma_mainloop(
    const __half* __restrict__ A, const __half* __restrict__ B,
    size_t lda, size_t ldb, int nch, uint32_t smem, float acc[4][8][4]) {

    const int tid = threadIdx.x;
    const int lane = tid & 31, wid = tid >> 5;
    const int wm = wid >> 1, wn = wid & 1;

    const uint32_t a_off = (uint32_t)(wm * 64 + (lane & 15)) * LDBY + ((lane & 16) ? 16u : 0u);
    const uint32_t b_off = (uint32_t)(wn * 64 + (lane & 7) + ((lane & 16) ? 8 : 0)) * LDBY
                         + ((lane & 8) ? 16u : 0u);

    // prologue: chunks 0, 1
#pragma unroll
    for (int s = 0; s < 2; s++) {
        if (s < nch) {
            uint32_t st = smem + s * STAGE_B;
            g2s_tile(st,           A, lda, s * 64, tid);
            g2s_tile(st + TILE_BY, B, ldb, s * 64, tid);
        }
        CP_COMMIT();
    }

    int sidx = 0;
    for (int c = 0; c < nch; c++) {
        CP_WAIT1();
        __syncthreads();

        const uint32_t st = smem + sidx * STAGE_B;
#pragma unroll
        for (int ks = 0; ks < 4; ks++) {
            const uint32_t ka = st + a_off + ks * 32;
            const uint32_t kb = st + TILE_BY + b_off + ks * 32;
            uint32_t ah[4][4], bb[8][2];
#pragma unroll
            for (int fm = 0; fm < 4; fm++)
                LDSM4(ah[fm][0], ah[fm][1], ah[fm][2], ah[fm][3], ka + fm * 16 * LDBY);
#pragma unroll
            for (int p = 0; p < 4; p++)
                LDSM4(bb[2*p][0], bb[2*p][1], bb[2*p+1][0], bb[2*p+1][1], kb + p * 16 * LDBY);
#pragma unroll
            for (int fm = 0; fm < 4; fm++)
#pragma unroll
                for (int fn = 0; fn < 8; fn++) mma_f16(acc[fm][fn], ah[fm], bb[fn]);
        }

        // prefetch chunk c+2 into stage (sidx+2)%3 (safe: all warps passed the
        // barrier above, so reads of that stage from iteration c-1 are done)
        if (c + 2 < nch) {
            int s2 = sidx + 2; if (s2 >= NSTAGE) s2 -= NSTAGE;
            uint32_t stw = smem + s2 * STAGE_B;
            const int k0 = (c + 2) * 64;
            g2s_tile(stw,           A, lda, k0, tid);
            g2s_tile(stw + TILE_BY, B, ldb, k0, tid);
        }
        CP_COMMIT();
        if (++sidx == NSTAGE) sidx = 0;
    }
}

#define ZERO_ACC(acc) \
    do { _Pragma("unroll") for (int i = 0; i < 4; i++) \
         _Pragma("unroll") for (int j = 0; j < 8; j++) \
         _Pragma("unroll") for (int r = 0; r < 4; r++) (acc)[i][j][r] = 0.0f; } while (0)

// ---------------------------------------------------------------------------
// Kernel 0: convert x, Wq, Wk, Wv to fp16
// ---------------------------------------------------------------------------
__global__ __launch_bounds__(256) void convert_all(
    const float* __restrict__ x, const float* __restrict__ wq,
    const float* __restrict__ wk, const float* __restrict__ wv) {
    const int which = blockIdx.y;
    const float* src = (which == 0) ? x : (which == 1) ? wq : (which == 2) ? wk : wv;
    __half* dst = (which == 0) ? g_x : g_w[which - 1];
    const int n = (which == 0) ? BB * SS * DD : DD * DD;
    for (int i = blockIdx.x * 256 + threadIdx.x; i * 2 < n; i += gridDim.x * 256) {
        float2 f = *(const float2*)(src + i * 2);
        __half2 h; h.x = __float2half(f.x); h.y = __float2half(f.y);
        *(__half2*)(dst + i * 2) = h;
    }
}

// ---------------------------------------------------------------------------
// Kernel 1: QKV.  z=0 -> Q, z=1 -> K, z=2 -> V^T (smem-staged transpose)
// ---------------------------------------------------------------------------
__global__ __launch_bounds__(128, 2) void qkv_mma() {
    extern __shared__ char smraw[];
    const uint32_t smem = (uint32_t)__cvta_generic_to_shared(smraw);
    const int z = blockIdx.z;
    const int m0 = blockIdx.y * 128;
    const int n0 = blockIdx.x * 128;

    float acc[4][8][4];
    ZERO_ACC(acc);

    mma_mainloop(g_x + (size_t)m0 * DD, g_w[z] + (size_t)n0 * DD,
                 DD, DD, DD / 64, smem, acc);

    const int lane = threadIdx.x & 31, wid = threadIdx.x >> 5;
    const int wm = wid >> 1, wn = wid & 1;
    const int g = lane >> 2, tg = lane & 3;

    if (z < 2) {
        __half* D = z ? g_k : g_q;
#pragma unroll
        for (int fm = 0; fm < 4; fm++)
#pragma unroll
            for (int fn = 0; fn < 8; fn++) {
                const int n = n0 + wn * 64 + fn * 8 + tg * 2;
#pragma unroll
                for (int half = 0; half < 2; half++) {
                    const int m = m0 + wm * 64 + fm * 16 + g + half * 8;
                    __half2 h2;
                    h2.x = __float2half(acc[fm][fn][half * 2]);
                    h2.y = __float2half(acc[fm][fn][half * 2 + 1]);
                    *(__half2*)(D + (size_t)m * DD + n) = h2;
                }
            }
    } else {
        // transpose 128x128 tile through smem, then coalesced store to V^T
        __syncthreads();                      // mainloop smem reads done
        __half* smt = (__half*)smraw;         // [n_local][m_local], stride 136
#pragma unroll
        for (int fm = 0; fm < 4; fm++)
#pragma unroll
            for (int fn = 0; fn < 8; fn++) {
                const int nl = wn * 64 + fn * 8 + tg * 2;
#pragma unroll
                for (int half = 0; half < 2; half++) {
                    const int ml = wm * 64 + fm * 16 + g + half * 8;
                    smt[(nl)     * 136 + ml] = __float2half(acc[fm][fn][half * 2]);
                    smt[(nl + 1) * 136 + ml] = __float2half(acc[fm][fn][half * 2 + 1]);
                }
            }
        __syncthreads();
        const int b = m0 >> 11, ml0 = m0 & (SS - 1);
        const size_t rowbase = (size_t)b * DD * SS + (size_t)(n0 + threadIdx.x) * SS + ml0;
#pragma unroll
        for (int c16 = 0; c16 < 16; c16++) {
            uint4 v = *(uint4*)(smt + threadIdx.x * 136 + c16 * 8);
            *(uint4*)(g_vT + rowbase + c16 * 8) = v;
        }
    }
}

// ---------------------------------------------------------------------------
// Kernel 2: causal scores -> p~ = exp(s/32) fp16, masked on diagonal tiles.
// Lower-triangular 128x128 tiles only (136 per batch).
// ---------------------------------------------------------------------------
__global__ __launch_bounds__(128, 2) void scores_mma() {
    extern __shared__ char smraw[];
    const uint32_t smem = (uint32_t)__cvta_generic_to_shared(smraw);
    const int t = blockIdx.x;
    int it = (int)floorf((sqrtf(8.0f * (float)t + 1.0f) - 1.0f) * 0.5f);
    while ((it + 1) * (it + 2) / 2 <= t) ++it;
    while (it * (it + 1) / 2 > t) --it;
    const int jt = t - it * (it + 1) / 2;
    const int b = blockIdx.y;
    const int m0 = it * 128, n0 = jt * 128;

    float acc[4][8][4];
    ZERO_ACC(acc);

    const size_t ao = ((size_t)b * SS + m0) * DD;
    const size_t bo = ((size_t)b * SS + n0) * DD;
    mma_mainloop(g_q + ao, g_k + bo, DD, DD, DD / 64, smem, acc);

    const int lane = threadIdx.x & 31, wid = threadIdx.x >> 5;
    const int wm = wid >> 1, wn = wid & 1;
    const int g = lane >> 2, tg = lane & 3;
    __half* C = g_ph + (size_t)b * SS * SS;
    const float alpha = 1.0f / 32.0f;
    const bool diag = (it == jt);

#pragma unroll
    for (int fm = 0; fm < 4; fm++)
#pragma unroll
        for (int fn = 0; fn < 8; fn++) {
            const int n = n0 + wn * 64 + fn * 8 + tg * 2;
#pragma unroll
            for (int half = 0; half < 2; half++) {
                const int m = m0 + wm * 64 + fm * 16 + g + half * 8;
                float e0 = __expf(acc[fm][fn][half * 2] * alpha);
                float e1 = __expf(acc[fm][fn][half * 2 + 1] * alpha);
                if (diag) {
                    if (n > m) e0 = 0.0f;
                    if (n + 1 > m) e1 = 0.0f;
                }
                __half2 h2; h2.x = __float2half(e0); h2.y = __float2half(e1);
                *(__half2*)(C + (size_t)m * SS + n) = h2;
            }
        }
}

// ---------------------------------------------------------------------------
// Kernel 3: row sums of p~ -> g_inv = 1/sum
// ---------------------------------------------------------------------------
__global__ __launch_bounds__(256) void rowsum() {
    const int i = blockIdx.x, b = blockIdx.y;
    const __half* row = g_ph + ((size_t)b * SS + i) * SS;
    const int tend = ((i >> 7) + 1) << 7;   // ceil(i+1, 128); masked zeros beyond i
    const int tid = threadIdx.x, lane = tid & 31, wid = tid >> 5;

    float s = 0.0f;
    for (int j = tid * 8; j < tend; j += 256 * 8) {
        uint4 v = *(const uint4*)(row + j);
        const __half2* h = (const __half2*)&v;
#pragma unroll
        for (int q = 0; q < 4; q++) {
            float2 f = __half22float2(h[q]);
            s += f.x + f.y;
        }
    }
#pragma unroll
    for (int o = 16; o; o >>= 1) s += __shfl_xor_sync(0xffffffffu, s, o);
    __shared__ float red[8];
    if (lane == 0) red[wid] = s;
    __syncthreads();
    if (tid == 0) {
        float v = red[0] + red[1] + red[2] + red[3] + red[4] + red[5] + red[6] + red[7];
        g_inv[b * SS + i] = 1.0f / v;
    }
}

// ---------------------------------------------------------------------------
// Kernel 4: O = (p~ @ V) * inv_row.  Longest row-tiles first.
// ---------------------------------------------------------------------------
__global__ __launch_bounds__(128, 2) void pv_mma(float* __restrict__ out) {
    extern __shared__ char smraw[];
    const uint32_t smem = (uint32_t)__cvta_generic_to_shared(smraw);
    const int b = blockIdx.z;
    const int it = (SS / 128 - 1) - blockIdx.y;   // 15..0, big tiles first
    const int m0 = it * 128;
    const int n0 = blockIdx.x * 128;
    const int nch = (it + 1) * 2;                 // kend = (it+1)*128, chunks of 64

    float acc[4][8][4];
    ZERO_ACC(acc);

    const size_t ao = ((size_t)b * SS + m0) * SS;
    const size_t bo = (size_t)b * DD * SS + (size_t)n0 * SS;
    mma_mainloop(g_ph + ao, g_vT + bo, SS, SS, nch, smem, acc);

    const int lane = threadIdx.x & 31, wid = threadIdx.x >> 5;
    const int wm = wid >> 1, wn = wid & 1;
    const int g = lane >> 2, tg = lane & 3;
    float* C = out + (size_t)b * SS * DD;

    float invm[4][2];
#pragma unroll
    for (int fm = 0; fm < 4; fm++)
#pragma unroll
        for (int half = 0; half < 2; half++)
            invm[fm][half] = g_inv[b * SS + m0 + wm * 64 + fm * 16 + g + half * 8];

#pragma unroll
    for (int fm = 0; fm < 4; fm++)
#pragma unroll
        for (int fn = 0; fn < 8; fn++) {
            const int n = n0 + wn * 64 + fn * 8 + tg * 2;
#pragma unroll
            for (int half = 0; half < 2; half++) {
                const int m = m0 + wm * 64 + fm * 16 + g + half * 8;
                float2 v;
                v.x = acc[fm][fn][half * 2]     * invm[fm][half];
                v.y = acc[fm][fn][half * 2 + 1] * invm[fm][half];
                *(float2*)(C + (size_t)m * DD + n) = v;
            }
        }
}

// ---------------------------------------------------------------------------
extern "C" void kernel_launch(void* const* d_in, const int* in_sizes, int n_in,
                              void* d_out, int out_size) {
    const float* x  = (const float*)d_in[0];
    const float* wq = (const float*)d_in[1];
    const float* wk = (const float*)d_in[2];
    const float* wv = (const float*)d_in[3];
    float* out = (float*)d_out;
    (void)in_sizes; (void)n_in; (void)out_size;

    static bool attr_done = false;
    if (!attr_done) {
        cudaFuncSetAttribute(qkv_mma,    cudaFuncAttributeMaxDynamicSharedMemorySize, SMEM_BYTES);
        cudaFuncSetAttribute(scores_mma, cudaFuncAttributeMaxDynamicSharedMemorySize, SMEM_BYTES);
        cudaFuncSetAttribute(pv_mma,     cudaFuncAttributeMaxDynamicSharedMemorySize, SMEM_BYTES);
        attr_done = true;
    }

    // 0) convert x, W to fp16
    convert_all<<<dim3(1024, 4), 256>>>(x, wq, wk, wv);

    // 1) Q, K, V^T projections
    qkv_mma<<<dim3(DD / 128, (BB * SS) / 128, 3), 128, SMEM_BYTES>>>();

    // 2) causal scores -> exp(s/32) fp16 (masked)
    const int ntri = (SS / 128) * (SS / 128 + 1) / 2;   // 136
    scores_mma<<<dim3(ntri, BB), 128, SMEM_BYTES>>>();

    // 3) row sums -> 1/sum
    rowsum<<<dim3(SS, BB), 256>>>();

    // 4) O = (p~ @ V) * inv
    pv_mma<<<dim3(DD / 128, SS / 128, BB), 128, SMEM_BYTES>>>(out);
}

// round 11
// speedup vs baseline: 3.3517x; 1.0231x over previous
#include <cuda_runtime.h>
#include <cuda_fp16.h>
#include <cstdint>
#include <math.h>

#define BB 4
#define SS 2048
#define DD 1024

#define LDBY 144                    // smem row stride bytes (128B data + 16B pad)
#define TILE_BY (128 * LDBY)        // 18432 B : 128x64 fp16 tile
#define NSTAGE 3
#define STAGE_B (2 * TILE_BY)       // A, B per stage = 36864
#define SMEM_BYTES (NSTAGE * STAGE_B)   // 110592 per CTA; 2 CTAs/SM = 221184

// ---------------------------------------------------------------------------
// Scratch (__device__ globals; allocation-free rule)
// ---------------------------------------------------------------------------
__device__ __align__(16) __half g_x[BB*SS*DD];
__device__ __align__(16) __half g_w[3][DD*DD];
__device__ __align__(16) __half g_q[BB*SS*DD];
__device__ __align__(16) __half g_k[BB*SS*DD];
__device__ __align__(16) __half g_vT[BB*DD*SS];     // V^T [b][d][s]
__device__ __align__(16) __half g_ph[BB*SS*SS];     // p~ = exp(s/32), causal-masked
__device__ __align__(16) float  g_sum[BB*SS];       // row sums (atomic-accumulated)

// ---------------------------------------------------------------------------
// PTX primitives
// ---------------------------------------------------------------------------
__device__ __forceinline__ void mma_f16(float* d, const uint32_t* a, const uint32_t* b) {
    asm volatile(
        "mma.sync.aligned.m16n8k16.row.col.f32.f16.f16.f32 "
        "{%0,%1,%2,%3}, {%4,%5,%6,%7}, {%8,%9}, {%0,%1,%2,%3};"
        : "+f"(d[0]), "+f"(d[1]), "+f"(d[2]), "+f"(d[3])
        : "r"(a[0]), "r"(a[1]), "r"(a[2]), "r"(a[3]), "r"(b[0]), "r"(b[1]));
}
#define LDSM4(r0, r1, r2, r3, addr) \
    asm volatile("ldmatrix.sync.aligned.m8n8.x4.shared.b16 {%0,%1,%2,%3}, [%4];" \
                 : "=r"(r0), "=r"(r1), "=r"(r2), "=r"(r3) : "r"(addr))
#define CP_ASYNC16(dst, src) \
    asm volatile("cp.async.cg.shared.global [%0], [%1], 16;" :: "r"(dst), "l"(src))
#define CP_COMMIT() asm volatile("cp.async.commit_group;" ::: "memory")
#define CP_WAIT1()  asm volatile("cp.async.wait_group 1;" ::: "memory")

// ---------------------------------------------------------------------------
// cp.async: one 128x64 fp16 tile (K-major, row stride ld elems). 128 threads.
// ---------------------------------------------------------------------------
__device__ __forceinline__ void g2s_tile(uint32_t dst, const __half* __restrict__ g,
                                         size_t ld, int k0, int tid) {
#pragma unroll
    for (int i = 0; i < 8; i++) {
        int slot = tid + (i << 7);      // 0..1023
        int row = slot >> 3;            // 0..127
        int c = slot & 7;               // 16B chunk
        CP_ASYNC16(dst + row * LDBY + c * 16, g + (size_t)row * ld + k0 + c * 8);
    }
}

// ---------------------------------------------------------------------------
// Mainloop: acc[4][8][4] += A[128,K] . B[128,K]^T  (fp16, K-chunk 64)
// 128 threads, 4 warps 2x2, warp tile 64x64, 3-stage cp.async pipeline,
// ONE __syncthreads per chunk (compute-then-prefetch ordering).
// ---------------------------------------------------------------------------
__device__ __forceinline__ void mma_mainloop(
    const __half* __restrict__ A, const __half* __restrict__ B,
    size_t lda, size_t ldb, int nch, uint32_t smem, float acc[4][8][4]) {

    const int tid = threadIdx.x;
    const int lane = tid & 31, wid = tid >> 5;
    const int wm = wid >> 1, wn = wid & 1;

    const uint32_t a_off = (uint32_t)(wm * 64 + (lane & 15)) * LDBY + ((lane & 16) ? 16u : 0u);
    const uint32_t b_off = (uint32_t)(wn * 64 + (lane & 7) + ((lane & 16) ? 8 : 0)) * LDBY
                         + ((lane & 8) ? 16u : 0u);

    // prologue: chunks 0, 1
#pragma unroll
    for (int s = 0; s < 2; s++) {
        if (s < nch) {
            uint32_t st = smem + s * STAGE_B;
            g2s_tile(st,           A, lda, s * 64, tid);
            g2s_tile(st + TILE_BY, B, ldb, s * 64, tid);
        }
        CP_COMMIT();
    }

    int sidx = 0;
    for (int c = 0; c < nch; c++) {
        CP_WAIT1();
        __syncthreads();

        const uint32_t st = smem + sidx * STAGE_B;
#pragma unroll
        for (int ks = 0; ks < 4; ks++) {
            const uint32_t ka = st + a_off + ks * 32;
            const uint32_t kb = st + TILE_BY + b_off + ks * 32;
            uint32_t ah[4][4], bb[8][2];
#pragma unroll
            for (int fm = 0; fm < 4; fm++)
                LDSM4(ah[fm][0], ah[fm][1], ah[fm][2], ah[fm][3], ka + fm * 16 * LDBY);
#pragma unroll
            for (int p = 0; p < 4; p++)
                LDSM4(bb[2*p][0], bb[2*p][1], bb[2*p+1][0], bb[2*p+1][1], kb + p * 16 * LDBY);
#pragma unroll
            for (int fm = 0; fm < 4; fm++)
#pragma unroll
                for (int fn = 0; fn < 8; fn++) mma_f16(acc[fm][fn], ah[fm], bb[fn]);
        }

        // prefetch chunk c+2 into stage (sidx+2)%3
        if (c + 2 < nch) {
            int s2 = sidx + 2; if (s2 >= NSTAGE) s2 -= NSTAGE;
            uint32_t stw = smem + s2 * STAGE_B;
            const int k0 = (c + 2) * 64;
            g2s_tile(stw,           A, lda, k0, tid);
            g2s_tile(stw + TILE_BY, B, ldb, k0, tid);
        }
        CP_COMMIT();
        if (++sidx == NSTAGE) sidx = 0;
    }
}

#define ZERO_ACC(acc) \
    do { _Pragma("unroll") for (int i = 0; i < 4; i++) \
         _Pragma("unroll") for (int j = 0; j < 8; j++) \
         _Pragma("unroll") for (int r = 0; r < 4; r++) (acc)[i][j][r] = 0.0f; } while (0)

// ---------------------------------------------------------------------------
// Kernel 0: convert x, Wq, Wk, Wv to fp16; zero g_sum
// ---------------------------------------------------------------------------
__global__ __launch_bounds__(256) void convert_all(
    const float* __restrict__ x, const float* __restrict__ wq,
    const float* __restrict__ wk, const float* __restrict__ wv) {
    const int which = blockIdx.y;
    const float* src = (which == 0) ? x : (which == 1) ? wq : (which == 2) ? wk : wv;
    __half* dst = (which == 0) ? g_x : g_w[which - 1];
    const int n = (which == 0) ? BB * SS * DD : DD * DD;
    for (int i = blockIdx.x * 256 + threadIdx.x; i * 2 < n; i += gridDim.x * 256) {
        float2 f = *(const float2*)(src + i * 2);
        __half2 h; h.x = __float2half(f.x); h.y = __float2half(f.y);
        *(__half2*)(dst + i * 2) = h;
    }
    if (which == 0) {
        for (int i = blockIdx.x * 256 + threadIdx.x; i < BB * SS; i += gridDim.x * 256)
            g_sum[i] = 0.0f;
    }
}

// ---------------------------------------------------------------------------
// Kernel 1: QKV.  z=0 -> Q, z=1 -> K, z=2 -> V^T (smem-staged transpose)
// ---------------------------------------------------------------------------
__global__ __launch_bounds__(128, 2) void qkv_mma() {
    extern __shared__ char smraw[];
    const uint32_t smem = (uint32_t)__cvta_generic_to_shared(smraw);
    const int z = blockIdx.z;
    const int m0 = blockIdx.y * 128;
    const int n0 = blockIdx.x * 128;

    float acc[4][8][4];
    ZERO_ACC(acc);

    mma_mainloop(g_x + (size_t)m0 * DD, g_w[z] + (size_t)n0 * DD,
                 DD, DD, DD / 64, smem, acc);

    const int lane = threadIdx.x & 31, wid = threadIdx.x >> 5;
    const int wm = wid >> 1, wn = wid & 1;
    const int g = lane >> 2, tg = lane & 3;

    if (z < 2) {
        __half* D = z ? g_k : g_q;
#pragma unroll
        for (int fm = 0; fm < 4; fm++)
#pragma unroll
            for (int fn = 0; fn < 8; fn++) {
                const int n = n0 + wn * 64 + fn * 8 + tg * 2;
#pragma unroll
                for (int half = 0; half < 2; half++) {
                    const int m = m0 + wm * 64 + fm * 16 + g + half * 8;
                    __half2 h2;
                    h2.x = __float2half(acc[fm][fn][half * 2]);
                    h2.y = __float2half(acc[fm][fn][half * 2 + 1]);
                    *(__half2*)(D + (size_t)m * DD + n) = h2;
                }
            }
    } else {
        // transpose 128x128 tile through smem, then coalesced store to V^T
        __syncthreads();                      // mainloop smem reads done
        __half* smt = (__half*)smraw;         // [n_local][m_local], stride 136
#pragma unroll
        for (int fm = 0; fm < 4; fm++)
#pragma unroll
            for (int fn = 0; fn < 8; fn++) {
                const int nl = wn * 64 + fn * 8 + tg * 2;
#pragma unroll
                for (int half = 0; half < 2; half++) {
                    const int ml = wm * 64 + fm * 16 + g + half * 8;
                    smt[(nl)     * 136 + ml] = __float2half(acc[fm][fn][half * 2]);
                    smt[(nl + 1) * 136 + ml] = __float2half(acc[fm][fn][half * 2 + 1]);
                }
            }
        __syncthreads();
        const int b = m0 >> 11, ml0 = m0 & (SS - 1);
        const size_t rowbase = (size_t)b * DD * SS + (size_t)(n0 + threadIdx.x) * SS + ml0;
#pragma unroll
        for (int c16 = 0; c16 < 16; c16++) {
            uint4 v = *(uint4*)(smt + threadIdx.x * 136 + c16 * 8);
            *(uint4*)(g_vT + rowbase + c16 * 8) = v;
        }
    }
}

// ---------------------------------------------------------------------------
// Kernel 2: causal scores -> p~ = exp(s/32) fp16 (masked) + fused row sums
// Lower-triangular 128x128 tiles only (136 per batch).
// ---------------------------------------------------------------------------
__global__ __launch_bounds__(128, 2) void scores_mma() {
    extern __shared__ char smraw[];
    const uint32_t smem = (uint32_t)__cvta_generic_to_shared(smraw);
    const int t = blockIdx.x;
    int it = (int)floorf((sqrtf(8.0f * (float)t + 1.0f) - 1.0f) * 0.5f);
    while ((it + 1) * (it + 2) / 2 <= t) ++it;
    while (it * (it + 1) / 2 > t) --it;
    const int jt = t - it * (it + 1) / 2;
    const int b = blockIdx.y;
    const int m0 = it * 128, n0 = jt * 128;

    float acc[4][8][4];
    ZERO_ACC(acc);

    const size_t ao = ((size_t)b * SS + m0) * DD;
    const size_t bo = ((size_t)b * SS + n0) * DD;
    mma_mainloop(g_q + ao, g_k + bo, DD, DD, DD / 64, smem, acc);

    const int lane = threadIdx.x & 31, wid = threadIdx.x >> 5;
    const int wm = wid >> 1, wn = wid & 1;
    const int g = lane >> 2, tg = lane & 3;
    __half* C = g_ph + (size_t)b * SS * SS;
    const float alpha = 1.0f / 32.0f;
    const bool diag = (it == jt);

#pragma unroll
    for (int fm = 0; fm < 4; fm++) {
#pragma unroll
        for (int half = 0; half < 2; half++) {
            const int m = m0 + wm * 64 + fm * 16 + g + half * 8;
            float rsum = 0.0f;
#pragma unroll
            for (int fn = 0; fn < 8; fn++) {
                const int n = n0 + wn * 64 + fn * 8 + tg * 2;
                float e0 = __expf(acc[fm][fn][half * 2] * alpha);
                float e1 = __expf(acc[fm][fn][half * 2 + 1] * alpha);
                if (diag) {
                    if (n > m) e0 = 0.0f;
                    if (n + 1 > m) e1 = 0.0f;
                }
                rsum += e0 + e1;
                __half2 h2; h2.x = __float2half(e0); h2.y = __float2half(e1);
                *(__half2*)(C + (size_t)m * SS + n) = h2;
            }
            // reduce across the 4 tg lanes (same row m)
            rsum += __shfl_xor_sync(0xffffffffu, rsum, 1);
            rsum += __shfl_xor_sync(0xffffffffu, rsum, 2);
            if (tg == 0) atomicAdd(&g_sum[b * SS + m], rsum);
        }
    }
}

// ---------------------------------------------------------------------------
// Kernel 3: O = (p~ @ V) / row_sum.  Longest row-tiles first.
// ---------------------------------------------------------------------------
__global__ __launch_bounds__(128, 2) void pv_mma(float* __restrict__ out) {
    extern __shared__ char smraw[];
    const uint32_t smem = (uint32_t)__cvta_generic_to_shared(smraw);
    const int b = blockIdx.z;
    const int it = (SS / 128 - 1) - blockIdx.y;   // 15..0, big tiles first
    const int m0 = it * 128;
    const int n0 = blockIdx.x * 128;
    const int nch = (it + 1) * 2;                 // kend = (it+1)*128, chunks of 64

    float acc[4][8][4];
    ZERO_ACC(acc);

    const size_t ao = ((size_t)b * SS + m0) * SS;
    const size_t bo = (size_t)b * DD * SS + (size_t)n0 * SS;
    mma_mainloop(g_ph + ao, g_vT + bo, SS, SS, nch, smem, acc);

    const int lane = threadIdx.x & 31, wid = threadIdx.x >> 5;
    const int wm = wid >> 1, wn = wid & 1;
    const int g = lane >> 2, tg = lane & 3;
    float* C = out + (size_t)b * SS * DD;

    float invm[4][2];
#pragma unroll
    for (int fm = 0; fm < 4; fm++)
#pragma unroll
        for (int half = 0; half < 2; half++)
            invm[fm][half] = 1.0f / g_sum[b * SS + m0 + wm * 64 + fm * 16 + g + half * 8];

#pragma unroll
    for (int fm = 0; fm < 4; fm++)
#pragma unroll
        for (int fn = 0; fn < 8; fn++) {
            const int n = n0 + wn * 64 + fn * 8 + tg * 2;
#pragma unroll
            for (int half = 0; half < 2; half++) {
                const int m = m0 + wm * 64 + fm * 16 + g + half * 8;
                float2 v;
                v.x = acc[fm][fn][half * 2]     * invm[fm][half];
                v.y = acc[fm][fn][half * 2 + 1] * invm[fm][half];
                *(float2*)(C + (size_t)m * DD + n) = v;
            }
        }
}

// ---------------------------------------------------------------------------
extern "C" void kernel_launch(void* const* d_in, const int* in_sizes, int n_in,
                              void* d_out, int out_size) {
    const float* x  = (const float*)d_in[0];
    const float* wq = (const float*)d_in[1];
    const float* wk = (const float*)d_in[2];
    const float* wv = (const float*)d_in[3];
    float* out = (float*)d_out;
    (void)in_sizes; (void)n_in; (void)out_size;

    static bool attr_done = false;
    if (!attr_done) {
        cudaFuncSetAttribute(qkv_mma,    cudaFuncAttributeMaxDynamicSharedMemorySize, SMEM_BYTES);
        cudaFuncSetAttribute(scores_mma, cudaFuncAttributeMaxDynamicSharedMemorySize, SMEM_BYTES);
        cudaFuncSetAttribute(pv_mma,     cudaFuncAttributeMaxDynamicSharedMemorySize, SMEM_BYTES);
        attr_done = true;
    }

    // 0) convert x, W to fp16; zero row sums
    convert_all<<<dim3(1024, 4), 256>>>(x, wq, wk, wv);

    // 1) Q, K, V^T projections
    qkv_mma<<<dim3(DD / 128, (BB * SS) / 128, 3), 128, SMEM_BYTES>>>();

    // 2) causal scores -> exp(s/32) fp16 (masked) + fused row sums
    const int ntri = (SS / 128) * (SS / 128 + 1) / 2;   // 136
    scores_mma<<<dim3(ntri, BB), 128, SMEM_BYTES>>>();

    // 3) O = (p~ @ V) / sum
    pv_mma<<<dim3(DD / 128, SS / 128, BB), 128, SMEM_BYTES>>>(out);
}